// round 12
// baseline (speedup 1.0000x reference)
#include <cuda_runtime.h>
#include <cuda_bf16.h>
#include <math.h>
#include <stdint.h>

// Problem constants
#define NR 64
#define NT 8
#define LD 128
#define LP 16
#define LT 144          // LD + LP
#define BSZ 512
#define MM 1024
#define NN 2048         // LDPC_N

#define SQ2F 1.41421356237309504880f
#define INV_SQ2F 0.70710678118654752440f

// -------- scratch (device globals; no runtime allocation) --------
__device__ float g_Ur[128 * 128];
__device__ float g_UrT[128 * 128];
__device__ float g_F[BSZ * NN];       // fbres permuted: [b][n]
__device__ float g_Vs[BSZ * MM];      // theta - z - lambda1
__device__ float g_AT[NN * MM];       // A^T
__device__ float g_HGT[BSZ * 24 * 128];
__device__ float g_T[BSZ * 24 * 128];
__device__ float g_EF[BSZ * 128];
__device__ float g_UrHvT[BSZ * 8 * 128];
__device__ float g_C1[2 * BSZ * NN];  // split-K partials for gemm1
__device__ float g_C2[2 * BSZ * MM];  // split-K partials for gemm2

// ================= mma.sync helpers =================
__device__ __forceinline__ uint32_t smem_to_u32(const void* smem_ptr) {
    uint32_t addr;
    asm("{ .reg .u64 tmp; cvta.to.shared.u64 tmp, %1; cvt.u32.u64 %0, tmp; }"
        : "=r"(addr) : "l"(smem_ptr));
    return addr;
}

__device__ __forceinline__ void cp16(uint32_t s, const float* g) {
    asm volatile("cp.async.cg.shared.global [%0], [%1], 16;" :: "r"(s), "l"(g) : "memory");
}
#define CP_COMMIT() asm volatile("cp.async.commit_group;" ::: "memory")
#define CP_WAIT1()  asm volatile("cp.async.wait_group 1;" ::: "memory")
#define CP_WAIT0()  asm volatile("cp.async.wait_group 0;" ::: "memory")

__device__ __forceinline__ uint32_t f2tf(float f) {
    uint32_t r;
    asm("cvt.rna.tf32.f32 %0, %1;" : "=r"(r) : "f"(f));
    return r;
}

__device__ __forceinline__ void mma_tf32(float* c, const uint32_t* a, const uint32_t* b) {
    asm volatile(
        "mma.sync.aligned.m16n8k8.row.col.f32.tf32.tf32.f32 "
        "{%0,%1,%2,%3}, {%4,%5,%6,%7}, {%8,%9}, {%0,%1,%2,%3};"
        : "+f"(c[0]), "+f"(c[1]), "+f"(c[2]), "+f"(c[3])
        : "r"(a[0]), "r"(a[1]), "r"(a[2]), "r"(a[3]), "r"(b[0]), "r"(b[1]));
}

// ---- shared tile mainloop: C[64x64] += P[64,klen] * Q[64,klen]^T, row stride ld ----
#define TILE_F (64 * 20)
template<bool PRECISE>
__device__ __forceinline__ void tile_gemm(const float* __restrict__ Pg0,
                                          const float* __restrict__ Qg0,
                                          int ld, int klen, float c[2][4][4],
                                          float* sP, float* sQ)
{
    const int tid = threadIdx.x;
    const int lane = tid & 31, wid = tid >> 5;
    const int wm = wid & 1, wn = wid >> 1;
    const int lrow = tid >> 2, lquad = tid & 3;

    uint32_t sPb = smem_to_u32(sP), sQb = smem_to_u32(sQ);
    const int NK = klen >> 4;
    const float* Pg = Pg0 + (size_t)lrow * ld + lquad * 4;
    const float* Qg = Qg0 + (size_t)lrow * ld + lquad * 4;
    const uint32_t spA0 = sPb + (uint32_t)(lrow * 20 + lquad * 4) * 4;
    const uint32_t spA1 = sPb + (uint32_t)((lrow + 32) * 20 + lquad * 4) * 4;
    const uint32_t sqA0 = sQb + (uint32_t)(lrow * 20 + lquad * 4) * 4;
    const uint32_t sqA1 = sQb + (uint32_t)((lrow + 32) * 20 + lquad * 4) * 4;

    {
        const float* p = Pg;  const float* q = Qg;
        cp16(spA0, p); cp16(spA1, p + (size_t)32 * ld);
        cp16(sqA0, q); cp16(sqA1, q + (size_t)32 * ld);
        CP_COMMIT();
        p = Pg + 16; q = Qg + 16;
        uint32_t off = TILE_F * 4;
        cp16(spA0 + off, p); cp16(spA1 + off, p + (size_t)32 * ld);
        cp16(sqA0 + off, q); cp16(sqA1 + off, q + (size_t)32 * ld);
        CP_COMMIT();
    }

    const int arow = lane >> 2, acol = lane & 3;
    for (int kt = 0; kt < NK; kt++) {
        CP_WAIT1();
        __syncthreads();
        const float* Pbuf = sP + (kt & 1) * TILE_F;
        const float* Qbuf = sQ + (kt & 1) * TILE_F;
        #pragma unroll
        for (int ks = 0; ks < 2; ks++) {
            const int k0 = ks * 8 + acol;
            uint32_t a[2][4], bq[4][2];
            uint32_t al[2][4], bl[4][2];
            #pragma unroll
            for (int mt = 0; mt < 2; mt++) {
                const int m = wm * 32 + mt * 16 + arow;
                float v0 = Pbuf[m * 20 + k0];
                float v1 = Pbuf[(m + 8) * 20 + k0];
                float v2 = Pbuf[m * 20 + k0 + 4];
                float v3 = Pbuf[(m + 8) * 20 + k0 + 4];
                a[mt][0] = f2tf(v0); a[mt][1] = f2tf(v1);
                a[mt][2] = f2tf(v2); a[mt][3] = f2tf(v3);
                if (PRECISE) {
                    al[mt][0] = f2tf(v0 - __uint_as_float(a[mt][0]));
                    al[mt][1] = f2tf(v1 - __uint_as_float(a[mt][1]));
                    al[mt][2] = f2tf(v2 - __uint_as_float(a[mt][2]));
                    al[mt][3] = f2tf(v3 - __uint_as_float(a[mt][3]));
                }
            }
            #pragma unroll
            for (int nt = 0; nt < 4; nt++) {
                const int n = wn * 32 + nt * 8 + arow;
                float w0 = Qbuf[n * 20 + k0];
                float w1 = Qbuf[n * 20 + k0 + 4];
                bq[nt][0] = f2tf(w0); bq[nt][1] = f2tf(w1);
                if (PRECISE) {
                    bl[nt][0] = f2tf(w0 - __uint_as_float(bq[nt][0]));
                    bl[nt][1] = f2tf(w1 - __uint_as_float(bq[nt][1]));
                }
            }
            #pragma unroll
            for (int mt = 0; mt < 2; mt++)
                #pragma unroll
                for (int nt = 0; nt < 4; nt++) {
                    if (PRECISE) {
                        mma_tf32(c[mt][nt], a[mt], bl[nt]);
                        mma_tf32(c[mt][nt], al[mt], bq[nt]);
                    }
                    mma_tf32(c[mt][nt], a[mt], bq[nt]);
                }
        }
        __syncthreads();
        if (kt + 2 < NK) {
            uint32_t off = (uint32_t)((kt & 1) * TILE_F) * 4;
            const float* p = Pg + (kt + 2) * 16;
            const float* q = Qg + (kt + 2) * 16;
            cp16(spA0 + off, p); cp16(spA1 + off, p + (size_t)32 * ld);
            cp16(sqA0 + off, q); cp16(sqA1 + off, q + (size_t)32 * ld);
        }
        CP_COMMIT();
    }
    CP_WAIT0();
}

// ================= prep: Ur/UrT + Vs + AT + acc =================
__global__ __launch_bounds__(256)
void prep_kernel(const float* __restrict__ rUr, const float* __restrict__ iUr,
                 const float* __restrict__ theta, const float* __restrict__ z,
                 const float* __restrict__ l1, const float* __restrict__ A,
                 const float* __restrict__ accnew_in, float* __restrict__ out_acc)
{
    __shared__ float t[32][33];
    const int bi = blockIdx.x;
    const int tid = threadIdx.x;

    if (bi < 64) {
        int e = bi * 256 + tid;
        int i = e >> 7, j = e & 127;
        float v, vt;
        if (i < 64) v = (j < 64) ? rUr[i * 64 + j] : -iUr[i * 64 + (j - 64)];
        else        v = (j < 64) ? iUr[(i - 64) * 64 + j] : rUr[(i - 64) * 64 + (j - 64)];
        g_Ur[e] = v;
        if (i < 64) vt = (j < 64) ? rUr[j * 64 + i] : iUr[(j - 64) * 64 + i];
        else        vt = (j < 64) ? -iUr[j * 64 + (i - 64)] : rUr[(j - 64) * 64 + (i - 64)];
        g_UrT[e] = vt;
    } else if (bi < 2112) {
        int e = (bi - 64) * 256 + tid;
        int m = e & (MM - 1);
        g_Vs[e] = theta[m] - z[e] - l1[e];
    } else if (bi < 4160) {
        int idx = bi - 2112;
        int n0 = (idx & 63) * 32, m0 = (idx >> 6) * 32;
        int tx = tid & 31, ty = tid >> 5;
        #pragma unroll
        for (int q = 0; q < 4; q++)
            t[ty + 8 * q][tx] = A[(size_t)(m0 + ty + 8 * q) * NN + n0 + tx];
        __syncthreads();
        #pragma unroll
        for (int q = 0; q < 4; q++)
            g_AT[(size_t)(n0 + ty + 8 * q) * MM + m0 + tx] = t[tx][ty + 8 * q];
    } else {
        if (tid == 0) out_acc[0] = accnew_in[0];
    }
}

// ================= K1a: per-batch front phases, 2 CTAs/batch =================
__global__ __launch_bounds__(256)
void k1a_kernel(const float* __restrict__ XXp, const float* __restrict__ YYp,
                const float* __restrict__ H,
                const float* __restrict__ rUt, const float* __restrict__ iUt)
{
    __shared__ float sXXp[16 * LT];
    __shared__ float sUtXT[LT * 16];
    __shared__ float sS[256];
    __shared__ float sCh2[2][64 * 20];
    __shared__ float sUt[128];

    const int b = blockIdx.x >> 1;
    const int half = blockIdx.x & 1;
    const int tid = threadIdx.x;

    const float* XXpb = XXp + (size_t)b * 16 * LT;
    for (int i = tid; i < 16 * LT; i += 256) sXXp[i] = XXpb[i];
    if (tid < 128) sUt[tid] = (tid < 64) ? rUt[tid] : iUt[tid - 64];

    const float* YYpb = YYp + (size_t)b * 128 * LT + (size_t)half * 64 * LT;
    const uint32_t chBase = smem_to_u32(sCh2);
    {
        int row = tid >> 2, seg = tid & 3;
        cp16(chBase + (uint32_t)(row * 20 + seg * 4) * 4, YYpb + row * LT + seg * 4);
    }
    CP_COMMIT();
    __syncthreads();

    for (int e = tid; e < 16 * LT; e += 256) {
        int i = e & 15, l = e >> 4;
        float acc = 0.f;
        if (i < 8) {
            #pragma unroll
            for (int k = 0; k < 8; k++) {
                acc += sUt[k * 8 + i] * sXXp[k * LT + l];
                acc += sUt[64 + k * 8 + i] * sXXp[(8 + k) * LT + l];
            }
        } else {
            int i2 = i - 8;
            #pragma unroll
            for (int k = 0; k < 8; k++) {
                acc -= sUt[64 + k * 8 + i2] * sXXp[k * LT + l];
                acc += sUt[k * 8 + i2] * sXXp[(8 + k) * LT + l];
            }
        }
        sUtXT[l * 16 + i] = acc;
    }
    __syncthreads();

    if (half == 0) {
        {
            int i = tid >> 4, j = tid & 15;
            float acc = 0.f;
            #pragma unroll 4
            for (int l = 0; l < LT; l++) acc += sUtXT[l * 16 + i] * sUtXT[l * 16 + j];
            sS[tid] = acc;
        }
        __syncthreads();

        if (tid < 128) {
            int q = tid & 63, k = q >> 3, t = q & 7;
            float v;
            if (tid < 64) v = sS[k * 16 + t] + sS[(8 + k) * 16 + 8 + t];
            else          v = sS[k * 16 + 8 + t] - sS[(8 + k) * 16 + t];
            g_EF[(size_t)b * 128 + tid] = v;
        }

        const float* Hb = H + (size_t)b * 1024;
        for (int e = tid; e < 1024; e += 256) {
            int c = e >> 7, k = e & 127;
            g_HGT[(size_t)b * 3072 + e] = Hb[k * 8 + c];
        }
    }

    // G^T[i][krow] for krow in [half*64, half*64+64) via 3xTF32 mma
    {
        const int lane = tid & 31, w = tid >> 5;
        const int arow = lane >> 2, acol = lane & 3;
        float cg[4] = {};
        for (int lc = 0; lc < 9; lc++) {
            if (lc + 1 < 9) {
                uint32_t off = (uint32_t)(((lc + 1) & 1) * (64 * 20)) * 4;
                int l0n = (lc + 1) * 16;
                int row = tid >> 2, seg = tid & 3;
                cp16(chBase + off + (uint32_t)(row * 20 + seg * 4) * 4,
                     YYpb + row * LT + l0n + seg * 4);
                CP_COMMIT();
                CP_WAIT1();
            } else {
                CP_WAIT0();
            }
            __syncthreads();
            const float* Ch = sCh2[lc & 1];
            #pragma unroll
            for (int ks = 0; ks < 2; ks++) {
                const int kg = lc * 16 + ks * 8 + acol;
                float av0 = sUtXT[kg * 16 + arow];
                float av1 = sUtXT[kg * 16 + arow + 8];
                float av2 = sUtXT[(kg + 4) * 16 + arow];
                float av3 = sUtXT[(kg + 4) * 16 + arow + 8];
                uint32_t ah[4] = {f2tf(av0), f2tf(av1), f2tf(av2), f2tf(av3)};
                uint32_t al[4] = {f2tf(av0 - __uint_as_float(ah[0])),
                                  f2tf(av1 - __uint_as_float(ah[1])),
                                  f2tf(av2 - __uint_as_float(ah[2])),
                                  f2tf(av3 - __uint_as_float(ah[3]))};
                const int n = w * 8 + arow;
                float bv0 = Ch[n * 20 + ks * 8 + acol];
                float bv1 = Ch[n * 20 + ks * 8 + acol + 4];
                uint32_t bh[2] = {f2tf(bv0), f2tf(bv1)};
                uint32_t bl[2] = {f2tf(bv0 - __uint_as_float(bh[0])),
                                  f2tf(bv1 - __uint_as_float(bh[1]))};
                mma_tf32(cg, ah, bl);
                mma_tf32(cg, al, bh);
                mma_tf32(cg, ah, bh);
            }
            __syncthreads();
        }
        float* dst = g_HGT + (size_t)b * 3072;
        const int col = half * 64 + w * 8 + (lane & 3) * 2;
        *(float2*)(dst + (8 + arow) * 128 + col) = make_float2(cg[0], cg[1]);
        *(float2*)(dst + (16 + arow) * 128 + col) = make_float2(cg[2], cg[3]);
    }
}

// ================= mega GEMM (3xTF32 precise) =================
__global__ __launch_bounds__(128)
void mega_gemm(const float* __restrict__ P, const float* __restrict__ Q,
               float* __restrict__ Out)
{
    __shared__ float buf[4 * TILE_F];
    const int m0 = blockIdx.x * 64;
    const int q0 = blockIdx.y * 64;
    float c[2][4][4] = {};
    tile_gemm<true>(P + (size_t)m0 * 128, Q + (size_t)q0 * 128, 128, 128, c,
                    buf, buf + 2 * TILE_F);
    __syncthreads();

    const int tid = threadIdx.x;
    const int lane = tid & 31, wid = tid >> 5;
    const int wm = wid & 1, wn = wid >> 1;
    #pragma unroll
    for (int mt = 0; mt < 2; mt++)
        #pragma unroll
        for (int nt = 0; nt < 4; nt++)
            #pragma unroll
            for (int k = 0; k < 4; k++) {
                int p = wm * 32 + mt * 16 + (lane >> 2) + (k >> 1) * 8;
                int q = wn * 32 + nt * 8 + (lane & 3) * 2 + (k & 1);
                buf[p * 68 + q] = c[mt][nt][k];
            }
    __syncthreads();
    #pragma unroll 4
    for (int i = 0; i < 32; i++) {
        int idx = i * 128 + tid;
        int p = idx & 63, q = idx >> 6;
        Out[(size_t)(q0 + q) * 128 + m0 + p] = buf[p * 68 + q];
    }
}

// ================= K3: Hv, D, Hvest, soft-threshold, UrHv (fused) =================
__global__ __launch_bounds__(256)
void k3_kernel(const float* __restrict__ sigma2,
               const float* __restrict__ rUt, const float* __restrict__ iUt,
               const float* __restrict__ tao_p, const float* __restrict__ eps_p)
{
    __shared__ float sTc[24 * 128];
    __shared__ float sEF[128];
    __shared__ float sUt[128];
    __shared__ float sHv[1024];
    __shared__ float sHve[1024];

    const int b = blockIdx.x;
    const int tid = threadIdx.x;
    const float tao = tao_p[0];

    for (int i = tid; i < 3072; i += 256) sTc[i] = g_T[(size_t)b * 3072 + i];
    if (tid < 128) {
        sEF[tid] = g_EF[(size_t)b * 128 + tid];
        sUt[tid] = (tid < 64) ? rUt[tid] : iUt[tid - 64];
    }
    __syncthreads();

    {
        const int r = tid >> 1, c0 = (tid & 1) * 4;
        #pragma unroll
        for (int c = c0; c < c0 + 4; c++) {
            float acc = 0.f;
            if (r < 64) {
                #pragma unroll
                for (int k = 0; k < 8; k++)
                    acc += sTc[k * 128 + r] * sUt[k * 8 + c] - sTc[k * 128 + 64 + r] * sUt[64 + k * 8 + c];
            } else {
                #pragma unroll
                for (int k = 0; k < 8; k++)
                    acc += sTc[k * 128 + r] * sUt[k * 8 + c] + sTc[k * 128 + r - 64] * sUt[64 + k * 8 + c];
            }
            sHv[r * 8 + c] = acc;
        }
    }
    __syncthreads();

    {
        const int r = tid >> 1, t0 = (tid & 1) * 4;
        #pragma unroll
        for (int t = t0; t < t0 + 4; t++) {
            float s = 0.f;
            if (r < 64) {
                #pragma unroll
                for (int k = 0; k < 8; k++)
                    s += sHv[r * 8 + k] * sEF[k * 8 + t] + sHv[(64 + r) * 8 + k] * sEF[64 + k * 8 + t];
                s -= sTc[(8 + t) * 128 + r] + sTc[(16 + t) * 128 + 64 + r];
            } else {
                int r2 = r - 64;
                #pragma unroll
                for (int k = 0; k < 8; k++)
                    s += sHv[r * 8 + k] * sEF[k * 8 + t] - sHv[r2 * 8 + k] * sEF[64 + k * 8 + t];
                s -= sTc[(8 + t) * 128 + r] - sTc[(16 + t) * 128 + r2];
            }
            sHve[r * 8 + t] = sHv[r * 8 + t] - tao * s;
        }
    }
    __syncthreads();

    {
        float thr = tao * eps_p[0] * sigma2[b];
        for (int e = tid; e < 512; e += 256) {
            float re = sHve[e], im = sHve[e + 512];
            float mag = sqrtf(re * re + im * im);
            float s = fmaxf(mag - thr, 0.f) / mag;
            sHve[e] = re * s;
            sHve[e + 512] = im * s;
        }
    }
    __syncthreads();

    // UrHv = Ur @ Hvest ; Ur[r][k] = g_UrT[k*128 + r] (coalesced) -> sHv
    {
        const int r = tid >> 1, c0 = (tid & 1) * 4;
        float acc[4] = {};
        #pragma unroll 4
        for (int k = 0; k < 128; k++) {
            float w = g_UrT[k * 128 + r];
            float4 h = *(const float4*)&sHve[k * 8 + c0];
            acc[0] += w * h.x; acc[1] += w * h.y; acc[2] += w * h.z; acc[3] += w * h.w;
        }
        #pragma unroll
        for (int q = 0; q < 4; q++) sHv[r * 8 + c0 + q] = acc[q];
    }
    __syncthreads();

    for (int i = tid; i < 1024; i += 256) {
        int c = i >> 7, r = i & 127;
        g_UrHvT[(size_t)b * 1024 + i] = sHv[r * 8 + c];
    }
}

// ================= K5: H_new, W, WTW, F via mma (512 thr) =================
#define CPAD 136
#define CHK (16 * CPAD)
__global__ __launch_bounds__(512)
void k5_kernel(const float* __restrict__ X, const float* __restrict__ Y,
               const float* __restrict__ lambda_W,
               const float* __restrict__ rUt, const float* __restrict__ iUt,
               const float* __restrict__ factor_p,
               float* __restrict__ out_Hnew, float* __restrict__ out_lamW)
{
    __shared__ float sUc[1024];
    __shared__ float sUt[128];
    __shared__ float sHN[1024];
    __shared__ float sW[128 * 24];
    __shared__ float sWTW[256];
    __shared__ float sX[2048];
    __shared__ float sCh[2][CHK];

    const int b = blockIdx.x;
    const int tid = threadIdx.x;

    const float* Yb = Y + (size_t)b * 128 * LD;
    const uint32_t chBase = smem_to_u32(sCh);
    {
        int row = tid >> 5, seg = tid & 31;
        cp16(chBase + (uint32_t)(row * CPAD + seg * 4) * 4, Yb + row * 128 + seg * 4);
    }
    CP_COMMIT();

    for (int i = tid; i < 1024; i += 512) sUc[i] = g_UrHvT[(size_t)b * 1024 + i];
    {
        const float* Xb = X + (size_t)b * 16 * LD;
        for (int e = tid; e < 2048; e += 512) sX[e] = Xb[e];
    }
    if (tid < 128) sUt[tid] = (tid < 64) ? rUt[tid] : iUt[tid - 64];
    __syncthreads();

    {
        const int r = tid >> 2, c0 = (tid & 3) * 2;
        #pragma unroll
        for (int c = c0; c < c0 + 2; c++) {
            float acc = 0.f;
            if (r < 64) {
                #pragma unroll
                for (int k = 0; k < 8; k++)
                    acc += sUc[k * 128 + r] * sUt[c * 8 + k] + sUc[k * 128 + 64 + r] * sUt[64 + c * 8 + k];
            } else {
                #pragma unroll
                for (int k = 0; k < 8; k++)
                    acc += sUc[k * 128 + r] * sUt[c * 8 + k] - sUc[k * 128 + r - 64] * sUt[64 + c * 8 + k];
            }
            sHN[r * 8 + c] = acc;
            out_Hnew[(size_t)b * 1024 + r * 8 + c] = acc;
        }
    }
    __syncthreads();

    for (int e = tid; e < 2048; e += 512) {
        int r = e >> 4, i = e & 15;
        float v;
        if (r < 64) v = (i < 8) ? sHN[r * 8 + i] : -sHN[(64 + r) * 8 + (i - 8)];
        else        v = (i < 8) ? sHN[r * 8 + i] : sHN[(r - 64) * 8 + (i - 8)];
        sW[r * 24 + i] = v;
    }
    __syncthreads();

    if (tid < 256) {
        int i = tid >> 4, j = tid & 15;
        float acc = 0.f;
        #pragma unroll 4
        for (int r = 0; r < 128; r++) acc += sW[r * 24 + i] * sW[r * 24 + j];
        sWTW[tid] = acc;
    }
    __syncthreads();

    {
        const int lane = tid & 31, w = tid >> 5;
        const int arow = lane >> 2, acol = lane & 3;
        float cf[4] = {};
        for (int rc = 0; rc < 8; rc++) {
            if (rc + 1 < 8) {
                uint32_t off = (uint32_t)(((rc + 1) & 1) * CHK) * 4;
                const float* src = Yb + (rc + 1) * 16 * 128;
                int row = tid >> 5, seg = tid & 31;
                cp16(chBase + off + (uint32_t)(row * CPAD + seg * 4) * 4,
                     src + row * 128 + seg * 4);
                CP_COMMIT();
                CP_WAIT1();
            } else {
                CP_WAIT0();
            }
            __syncthreads();
            const float* Ch = sCh[rc & 1];
            #pragma unroll
            for (int ks = 0; ks < 2; ks++) {
                const int kg = rc * 16 + ks * 8 + acol;
                float av0 = sW[kg * 24 + arow];
                float av1 = sW[kg * 24 + arow + 8];
                float av2 = sW[(kg + 4) * 24 + arow];
                float av3 = sW[(kg + 4) * 24 + arow + 8];
                uint32_t ah[4] = {f2tf(av0), f2tf(av1), f2tf(av2), f2tf(av3)};
                uint32_t al[4] = {f2tf(av0 - __uint_as_float(ah[0])),
                                  f2tf(av1 - __uint_as_float(ah[1])),
                                  f2tf(av2 - __uint_as_float(ah[2])),
                                  f2tf(av3 - __uint_as_float(ah[3]))};
                const int n = w * 8 + arow;
                float bv0 = Ch[(ks * 8 + acol) * CPAD + n];
                float bv1 = Ch[(ks * 8 + acol + 4) * CPAD + n];
                uint32_t bh[2] = {f2tf(bv0), f2tf(bv1)};
                uint32_t bl[2] = {f2tf(bv0 - __uint_as_float(bh[0])),
                                  f2tf(bv1 - __uint_as_float(bh[1]))};
                mma_tf32(cf, ah, bl);
                mma_tf32(cf, al, bh);
                mma_tf32(cf, ah, bh);
            }
            __syncthreads();
        }

        float lamW = factor_p[0] * lambda_W[b];
        float* Fb = g_F + (size_t)b * NN;
        float wt0[16], wt1[16];
        #pragma unroll
        for (int j = 0; j < 16; j++) {
            wt0[j] = sWTW[arow * 16 + j];
            wt1[j] = sWTW[(arow + 8) * 16 + j];
        }
        #pragma unroll
        for (int ls = 0; ls < 2; ls++) {
            const int l = w * 8 + (lane & 3) * 2 + ls;
            float xi[16];
            #pragma unroll
            for (int j = 0; j < 16; j++) xi[j] = sX[j * 128 + l];
            float v0 = cf[ls] + lamW * xi[arow];
            float v1 = cf[2 + ls] + lamW * xi[arow + 8];
            #pragma unroll
            for (int j = 0; j < 16; j++) {
                v0 -= wt0[j] * xi[j];
                v1 -= wt1[j] * xi[j];
            }
            *(float2*)(Fb + l * 16 + arow * 2) =
                make_float2(2.f * lamW - 2.f * SQ2F * v0,
                            2.f * lamW - 2.f * SQ2F * v1);
        }
        if (tid == 0) out_lamW[b] = lamW;
    }
}

// ================= split-K MMA GEMM1: partial C[b,n] =================
__global__ __launch_bounds__(128)
void mma_gemm1(float* __restrict__ dummy)
{
    __shared__ float sP[2 * TILE_F];
    __shared__ float sQ[2 * TILE_F];
    const int n0 = blockIdx.x * 64, b0 = blockIdx.y * 64, kh = blockIdx.z;
    float c[2][4][4] = {};
    tile_gemm<false>(g_Vs + (size_t)b0 * MM + kh * 512,
                     g_AT + (size_t)n0 * MM + kh * 512, MM, 512, c, sP, sQ);

    float* Cp = g_C1 + (size_t)kh * BSZ * NN;
    const int lane = threadIdx.x & 31, wid = threadIdx.x >> 5;
    const int wm = wid & 1, wn = wid >> 1;
    #pragma unroll
    for (int mt = 0; mt < 2; mt++)
        #pragma unroll
        for (int rr = 0; rr < 2; rr++) {
            const int b = b0 + wm * 32 + mt * 16 + (lane >> 2) + rr * 8;
            float* Cb = Cp + (size_t)b * NN;
            #pragma unroll
            for (int nt = 0; nt < 4; nt++) {
                const int n = n0 + wn * 32 + nt * 8 + (lane & 3) * 2;
                *(float2*)(Cb + n) = make_float2(c[mt][nt][rr * 2 + 0],
                                                 c[mt][nt][rr * 2 + 1]);
            }
        }
    (void)dummy;
}

// ================= epi1: combine partials -> u_new =================
__global__ void epi1_kernel(const float* __restrict__ La, const float* __restrict__ lamWv,
                            const float* __restrict__ rho_p, const float* __restrict__ kappa_p,
                            float* __restrict__ out_u)
{
    int idx = blockIdx.x * blockDim.x + threadIdx.x;
    if (idx >= BSZ * NN / 4) return;
    float4 p0 = ((const float4*)g_C1)[idx];
    float4 p1 = ((const float4*)(g_C1 + (size_t)BSZ * NN))[idx];
    int e4 = idx * 4;
    int b = e4 >> 11, n = e4 & 2047;
    float rho = rho_p[0], kappa = kappa_p[0];
    float lamW = lamWv[b];
    float den = 4.f * lamW - 2.f * kappa;
    float4 fb = ((const float4*)g_F)[idx];
    float4 la = *(const float4*)(La + n);
    float4 u;
    u.x = fminf(fmaxf((rho * (p0.x + p1.x) + fb.x - kappa) / (rho * la.x + den), 0.f), 1.f);
    u.y = fminf(fmaxf((rho * (p0.y + p1.y) + fb.y - kappa) / (rho * la.y + den), 0.f), 1.f);
    u.z = fminf(fmaxf((rho * (p0.z + p1.z) + fb.z - kappa) / (rho * la.z + den), 0.f), 1.f);
    u.w = fminf(fmaxf((rho * (p0.w + p1.w) + fb.w - kappa) / (rho * la.w + den), 0.f), 1.f);
    ((float4*)out_u)[idx] = u;
}

// ================= split-K MMA GEMM2: partial C[b,m] =================
__global__ __launch_bounds__(128)
void mma_gemm2(const float* __restrict__ A, const float* __restrict__ u_in)
{
    __shared__ float sP[2 * TILE_F];
    __shared__ float sQ[2 * TILE_F];
    const int m0 = blockIdx.x * 64, b0 = blockIdx.y * 64, kh = blockIdx.z;
    float c[2][4][4] = {};
    tile_gemm<false>(u_in + (size_t)b0 * NN + kh * 1024,
                     A + (size_t)m0 * NN + kh * 1024, NN, 1024, c, sP, sQ);

    float* Cp = g_C2 + (size_t)kh * BSZ * MM;
    const int lane = threadIdx.x & 31, wid = threadIdx.x >> 5;
    const int wm = wid & 1, wn = wid >> 1;
    #pragma unroll
    for (int mt = 0; mt < 2; mt++)
        #pragma unroll
        for (int rr = 0; rr < 2; rr++) {
            const int b = b0 + wm * 32 + mt * 16 + (lane >> 2) + rr * 8;
            float* Cb = Cp + (size_t)b * MM;
            #pragma unroll
            for (int nt = 0; nt < 4; nt++) {
                const int m = m0 + wn * 32 + nt * 8 + (lane & 3) * 2;
                *(float2*)(Cb + m) = make_float2(c[mt][nt][rr * 2 + 0],
                                                 c[mt][nt][rr * 2 + 1]);
            }
        }
}

// ================= epi2: combine partials -> z_new, lambda1_new =================
__global__ void epi2_kernel(const float* __restrict__ theta, const float* __restrict__ z_old,
                            const float* __restrict__ l1_old, const float* __restrict__ relax_p,
                            const float* __restrict__ acc_p,
                            float* __restrict__ out_z, float* __restrict__ out_l1)
{
    int idx = blockIdx.x * blockDim.x + threadIdx.x;
    if (idx >= BSZ * MM / 4) return;
    float4 p0 = ((const float4*)g_C2)[idx];
    float4 p1 = ((const float4*)(g_C2 + (size_t)BSZ * MM))[idx];
    int e4 = idx * 4;
    int m = e4 & 1023;
    float relax = relax_p[0], acc = acc_p[0];
    float4 th = *(const float4*)(theta + m);
    float4 zo = ((const float4*)z_old)[idx];
    float4 lo = ((const float4*)l1_old)[idx];
    float4 zn, ln;
    #define DO(comp) { \
        float ct = p0.comp + p1.comp; \
        float zt = th.comp - relax * ct - (1.f - relax) * (th.comp - zo.comp) - lo.comp; \
        float z1 = fmaxf(zt, 0.f); \
        float l1v = z1 - zt; \
        zn.comp = z1 + acc * (z1 - zo.comp); \
        ln.comp = l1v + acc * (l1v - lo.comp); }
    DO(x) DO(y) DO(z) DO(w)
    #undef DO
    ((float4*)out_z)[idx] = zn;
    ((float4*)out_l1)[idx] = ln;
}

// ================= xk: u -> X_new / XXp_new (smem transpose, coalesced) =================
__global__ __launch_bounds__(256)
void xk_kernel(const float* __restrict__ u_new, const float* __restrict__ rXp,
               const float* __restrict__ iXp,
               float* __restrict__ out_X, float* __restrict__ out_XXp)
{
    __shared__ float st[16 * 132];
    const int b = blockIdx.x;
    const int tid = threadIdx.x;
    const float* ub = u_new + (size_t)b * NN;
    for (int n = tid; n < 2048; n += 256) {
        float uv = ub[n];
        int l = n >> 4, t = (n >> 1) & 7, ci = n & 1;
        st[(ci * 8 + t) * 132 + l] = (1.f - 2.f * uv) * INV_SQ2F;
    }
    __syncthreads();
    float* Xb = out_X + (size_t)b * 2048;
    float* XXb = out_XXp + (size_t)b * 2304;
    for (int e = tid; e < 2048; e += 256) {
        int row = e >> 7, l = e & 127;
        float v = st[row * 132 + l];
        Xb[e] = v;
        XXb[row * 144 + l] = v;
    }
    // padding cols 128..143 from pilots
    {
        int e = tid;
        int tt = e >> 5, ci = (e >> 4) & 1, lp = e & 15;
        float v = ci ? iXp[(size_t)b * 128 + tt * 16 + lp]
                     : rXp[(size_t)b * 128 + tt * 16 + lp];
        XXb[(ci * 8 + tt) * 144 + 128 + lp] = v;
    }
}

// ================= launch =================
extern "C" void kernel_launch(void* const* d_in, const int* in_sizes, int n_in,
                              void* d_out, int out_size) {
    (void)in_sizes; (void)n_in; (void)out_size;
    const float* sigma2   = (const float*)d_in[0];
    const float* X        = (const float*)d_in[1];
    const float* XXp      = (const float*)d_in[2];
    const float* Y        = (const float*)d_in[3];
    const float* YYp      = (const float*)d_in[4];
    const float* rXp      = (const float*)d_in[5];
    const float* iXp      = (const float*)d_in[6];
    const float* H        = (const float*)d_in[7];
    const float* lambda_W = (const float*)d_in[8];
    const float* z        = (const float*)d_in[10];
    const float* lambda1  = (const float*)d_in[11];
    const float* acc_new  = (const float*)d_in[12];
    const float* A        = (const float*)d_in[13];
    const float* Lambda_A = (const float*)d_in[14];
    const float* theta    = (const float*)d_in[15];
    const float* rUr      = (const float*)d_in[16];
    const float* iUr      = (const float*)d_in[17];
    const float* rUt      = (const float*)d_in[18];
    const float* iUt      = (const float*)d_in[19];
    const float* rho      = (const float*)d_in[20];
    const float* kappa    = (const float*)d_in[21];
    const float* epsilon  = (const float*)d_in[22];
    const float* tao      = (const float*)d_in[23];
    const float* factor   = (const float*)d_in[24];
    const float* relax    = (const float*)d_in[25];
    const float* acc      = (const float*)d_in[26];

    float* out = (float*)d_out;
    float* out_X    = out;
    float* out_XXp  = out + 1048576;
    float* out_H    = out + 2228224;
    float* out_lamW = out + 2752512;
    float* out_u    = out + 2753024;
    float* out_z    = out + 3801600;
    float* out_l1   = out + 4325888;
    float* out_acc  = out + 4850176;

    float* dg_Ur, *dg_UrT, *dg_HGT, *dg_T;
    cudaGetSymbolAddress((void**)&dg_Ur, g_Ur);
    cudaGetSymbolAddress((void**)&dg_UrT, g_UrT);
    cudaGetSymbolAddress((void**)&dg_HGT, g_HGT);
    cudaGetSymbolAddress((void**)&dg_T, g_T);

    prep_kernel<<<4161, 256>>>(rUr, iUr, theta, z, lambda1, A, acc_new, out_acc);
    k1a_kernel<<<BSZ * 2, 256>>>(XXp, YYp, H, rUt, iUt);
    mega_gemm<<<dim3(2, BSZ * 24 / 64), 128>>>(dg_UrT, dg_HGT, dg_T);
    k3_kernel<<<BSZ, 256>>>(sigma2, rUt, iUt, tao, epsilon);
    k5_kernel<<<BSZ, 512>>>(X, Y, lambda_W, rUt, iUt, factor, out_H, out_lamW);
    mma_gemm1<<<dim3(NN / 64, BSZ / 64, 2), 128>>>(nullptr);
    epi1_kernel<<<(BSZ * NN / 4 + 255) / 256, 256>>>(Lambda_A, out_lamW, rho, kappa, out_u);
    mma_gemm2<<<dim3(MM / 64, BSZ / 64, 2), 128>>>(A, out_u);
    epi2_kernel<<<(BSZ * MM / 4 + 255) / 256, 256>>>(theta, z, lambda1, relax, acc,
                                                     out_z, out_l1);
    xk_kernel<<<BSZ, 256>>>(out_u, rXp, iXp, out_X, out_XXp);
}

// round 13
// speedup vs baseline: 1.0105x; 1.0105x over previous
#include <cuda_runtime.h>
#include <cuda_bf16.h>
#include <math.h>
#include <stdint.h>

// Problem constants
#define NR 64
#define NT 8
#define LD 128
#define LP 16
#define LT 144          // LD + LP
#define BSZ 512
#define MM 1024
#define NN 2048         // LDPC_N

#define SQ2F 1.41421356237309504880f
#define INV_SQ2F 0.70710678118654752440f

// -------- scratch (device globals; no runtime allocation) --------
__device__ float g_Ur[128 * 128];
__device__ float g_UrT[128 * 128];
__device__ float g_F[BSZ * NN];       // fbres permuted: [b][n]
__device__ float g_Vs[BSZ * MM];      // theta - z - lambda1
__device__ float g_AT[NN * MM];       // A^T
__device__ float g_HGT[BSZ * 24 * 128];
__device__ float g_T[BSZ * 24 * 128];
__device__ float g_EF[BSZ * 128];
__device__ float g_HveT[BSZ * 8 * 128];
__device__ float g_UrHvT[BSZ * 8 * 128];
__device__ float g_C1[2 * BSZ * NN];  // split-K partials for gemm1
__device__ float g_C2[2 * BSZ * MM];  // split-K partials for gemm2

// ================= mma.sync helpers =================
__device__ __forceinline__ uint32_t smem_to_u32(const void* smem_ptr) {
    uint32_t addr;
    asm("{ .reg .u64 tmp; cvta.to.shared.u64 tmp, %1; cvt.u32.u64 %0, tmp; }"
        : "=r"(addr) : "l"(smem_ptr));
    return addr;
}

__device__ __forceinline__ void cp16(uint32_t s, const float* g) {
    asm volatile("cp.async.cg.shared.global [%0], [%1], 16;" :: "r"(s), "l"(g) : "memory");
}
#define CP_COMMIT() asm volatile("cp.async.commit_group;" ::: "memory")
#define CP_WAIT1()  asm volatile("cp.async.wait_group 1;" ::: "memory")
#define CP_WAIT0()  asm volatile("cp.async.wait_group 0;" ::: "memory")

__device__ __forceinline__ uint32_t f2tf(float f) {
    uint32_t r;
    asm("cvt.rna.tf32.f32 %0, %1;" : "=r"(r) : "f"(f));
    return r;
}

__device__ __forceinline__ void mma_tf32(float* c, const uint32_t* a, const uint32_t* b) {
    asm volatile(
        "mma.sync.aligned.m16n8k8.row.col.f32.tf32.tf32.f32 "
        "{%0,%1,%2,%3}, {%4,%5,%6,%7}, {%8,%9}, {%0,%1,%2,%3};"
        : "+f"(c[0]), "+f"(c[1]), "+f"(c[2]), "+f"(c[3])
        : "r"(a[0]), "r"(a[1]), "r"(a[2]), "r"(a[3]), "r"(b[0]), "r"(b[1]));
}

// ---- shared tile mainloop: C[64x64] += P[64,klen] * Q[64,klen]^T, row stride ld ----
#define TILE_F (64 * 20)
template<bool PRECISE>
__device__ __forceinline__ void tile_gemm(const float* __restrict__ Pg0,
                                          const float* __restrict__ Qg0,
                                          int ld, int klen, float c[2][4][4],
                                          float* sP, float* sQ)
{
    const int tid = threadIdx.x;
    const int lane = tid & 31, wid = tid >> 5;
    const int wm = wid & 1, wn = wid >> 1;
    const int lrow = tid >> 2, lquad = tid & 3;

    uint32_t sPb = smem_to_u32(sP), sQb = smem_to_u32(sQ);
    const int NK = klen >> 4;
    const float* Pg = Pg0 + (size_t)lrow * ld + lquad * 4;
    const float* Qg = Qg0 + (size_t)lrow * ld + lquad * 4;
    const uint32_t spA0 = sPb + (uint32_t)(lrow * 20 + lquad * 4) * 4;
    const uint32_t spA1 = sPb + (uint32_t)((lrow + 32) * 20 + lquad * 4) * 4;
    const uint32_t sqA0 = sQb + (uint32_t)(lrow * 20 + lquad * 4) * 4;
    const uint32_t sqA1 = sQb + (uint32_t)((lrow + 32) * 20 + lquad * 4) * 4;

    {
        const float* p = Pg;  const float* q = Qg;
        cp16(spA0, p); cp16(spA1, p + (size_t)32 * ld);
        cp16(sqA0, q); cp16(sqA1, q + (size_t)32 * ld);
        CP_COMMIT();
        p = Pg + 16; q = Qg + 16;
        uint32_t off = TILE_F * 4;
        cp16(spA0 + off, p); cp16(spA1 + off, p + (size_t)32 * ld);
        cp16(sqA0 + off, q); cp16(sqA1 + off, q + (size_t)32 * ld);
        CP_COMMIT();
    }

    const int arow = lane >> 2, acol = lane & 3;
    for (int kt = 0; kt < NK; kt++) {
        CP_WAIT1();
        __syncthreads();
        const float* Pbuf = sP + (kt & 1) * TILE_F;
        const float* Qbuf = sQ + (kt & 1) * TILE_F;
        #pragma unroll
        for (int ks = 0; ks < 2; ks++) {
            const int k0 = ks * 8 + acol;
            uint32_t a[2][4], bq[4][2];
            uint32_t al[2][4], bl[4][2];
            #pragma unroll
            for (int mt = 0; mt < 2; mt++) {
                const int m = wm * 32 + mt * 16 + arow;
                float v0 = Pbuf[m * 20 + k0];
                float v1 = Pbuf[(m + 8) * 20 + k0];
                float v2 = Pbuf[m * 20 + k0 + 4];
                float v3 = Pbuf[(m + 8) * 20 + k0 + 4];
                a[mt][0] = f2tf(v0); a[mt][1] = f2tf(v1);
                a[mt][2] = f2tf(v2); a[mt][3] = f2tf(v3);
                if (PRECISE) {
                    al[mt][0] = f2tf(v0 - __uint_as_float(a[mt][0]));
                    al[mt][1] = f2tf(v1 - __uint_as_float(a[mt][1]));
                    al[mt][2] = f2tf(v2 - __uint_as_float(a[mt][2]));
                    al[mt][3] = f2tf(v3 - __uint_as_float(a[mt][3]));
                }
            }
            #pragma unroll
            for (int nt = 0; nt < 4; nt++) {
                const int n = wn * 32 + nt * 8 + arow;
                float w0 = Qbuf[n * 20 + k0];
                float w1 = Qbuf[n * 20 + k0 + 4];
                bq[nt][0] = f2tf(w0); bq[nt][1] = f2tf(w1);
                if (PRECISE) {
                    bl[nt][0] = f2tf(w0 - __uint_as_float(bq[nt][0]));
                    bl[nt][1] = f2tf(w1 - __uint_as_float(bq[nt][1]));
                }
            }
            #pragma unroll
            for (int mt = 0; mt < 2; mt++)
                #pragma unroll
                for (int nt = 0; nt < 4; nt++) {
                    if (PRECISE) {
                        mma_tf32(c[mt][nt], a[mt], bl[nt]);
                        mma_tf32(c[mt][nt], al[mt], bq[nt]);
                    }
                    mma_tf32(c[mt][nt], a[mt], bq[nt]);
                }
        }
        __syncthreads();
        if (kt + 2 < NK) {
            uint32_t off = (uint32_t)((kt & 1) * TILE_F) * 4;
            const float* p = Pg + (kt + 2) * 16;
            const float* q = Qg + (kt + 2) * 16;
            cp16(spA0 + off, p); cp16(spA1 + off, p + (size_t)32 * ld);
            cp16(sqA0 + off, q); cp16(sqA1 + off, q + (size_t)32 * ld);
        }
        CP_COMMIT();
    }
    CP_WAIT0();
}

// ================= prep: Ur/UrT + Vs + AT + acc =================
__global__ __launch_bounds__(256)
void prep_kernel(const float* __restrict__ rUr, const float* __restrict__ iUr,
                 const float* __restrict__ theta, const float* __restrict__ z,
                 const float* __restrict__ l1, const float* __restrict__ A,
                 const float* __restrict__ accnew_in, float* __restrict__ out_acc)
{
    __shared__ float t[32][33];
    const int bi = blockIdx.x;
    const int tid = threadIdx.x;

    if (bi < 64) {
        int e = bi * 256 + tid;
        int i = e >> 7, j = e & 127;
        float v, vt;
        if (i < 64) v = (j < 64) ? rUr[i * 64 + j] : -iUr[i * 64 + (j - 64)];
        else        v = (j < 64) ? iUr[(i - 64) * 64 + j] : rUr[(i - 64) * 64 + (j - 64)];
        g_Ur[e] = v;
        if (i < 64) vt = (j < 64) ? rUr[j * 64 + i] : iUr[(j - 64) * 64 + i];
        else        vt = (j < 64) ? -iUr[j * 64 + (i - 64)] : rUr[(j - 64) * 64 + (i - 64)];
        g_UrT[e] = vt;
    } else if (bi < 2112) {
        int e = (bi - 64) * 256 + tid;
        int m = e & (MM - 1);
        g_Vs[e] = theta[m] - z[e] - l1[e];
    } else if (bi < 4160) {
        int idx = bi - 2112;
        int n0 = (idx & 63) * 32, m0 = (idx >> 6) * 32;
        int tx = tid & 31, ty = tid >> 5;
        #pragma unroll
        for (int q = 0; q < 4; q++)
            t[ty + 8 * q][tx] = A[(size_t)(m0 + ty + 8 * q) * NN + n0 + tx];
        __syncthreads();
        #pragma unroll
        for (int q = 0; q < 4; q++)
            g_AT[(size_t)(n0 + ty + 8 * q) * MM + m0 + tx] = t[tx][ty + 8 * q];
    } else {
        if (tid == 0) out_acc[0] = accnew_in[0];
    }
}

// ================= K1a: per-batch front phases, 2 CTAs/batch =================
__global__ __launch_bounds__(256)
void k1a_kernel(const float* __restrict__ XXp, const float* __restrict__ YYp,
                const float* __restrict__ H,
                const float* __restrict__ rUt, const float* __restrict__ iUt)
{
    __shared__ float sXXp[16 * LT];
    __shared__ float sUtXT[LT * 16];
    __shared__ float sS[256];
    __shared__ float sCh2[2][64 * 20];
    __shared__ float sUt[128];

    const int b = blockIdx.x >> 1;
    const int half = blockIdx.x & 1;
    const int tid = threadIdx.x;

    const float* XXpb = XXp + (size_t)b * 16 * LT;
    for (int i = tid; i < 16 * LT; i += 256) sXXp[i] = XXpb[i];
    if (tid < 128) sUt[tid] = (tid < 64) ? rUt[tid] : iUt[tid - 64];

    const float* YYpb = YYp + (size_t)b * 128 * LT + (size_t)half * 64 * LT;
    const uint32_t chBase = smem_to_u32(sCh2);
    {
        int row = tid >> 2, seg = tid & 3;
        cp16(chBase + (uint32_t)(row * 20 + seg * 4) * 4, YYpb + row * LT + seg * 4);
    }
    CP_COMMIT();
    __syncthreads();

    for (int e = tid; e < 16 * LT; e += 256) {
        int i = e & 15, l = e >> 4;
        float acc = 0.f;
        if (i < 8) {
            #pragma unroll
            for (int k = 0; k < 8; k++) {
                acc += sUt[k * 8 + i] * sXXp[k * LT + l];
                acc += sUt[64 + k * 8 + i] * sXXp[(8 + k) * LT + l];
            }
        } else {
            int i2 = i - 8;
            #pragma unroll
            for (int k = 0; k < 8; k++) {
                acc -= sUt[64 + k * 8 + i2] * sXXp[k * LT + l];
                acc += sUt[k * 8 + i2] * sXXp[(8 + k) * LT + l];
            }
        }
        sUtXT[l * 16 + i] = acc;
    }
    __syncthreads();

    if (half == 0) {
        {
            int i = tid >> 4, j = tid & 15;
            float acc = 0.f;
            #pragma unroll 4
            for (int l = 0; l < LT; l++) acc += sUtXT[l * 16 + i] * sUtXT[l * 16 + j];
            sS[tid] = acc;
        }
        __syncthreads();

        if (tid < 128) {
            int q = tid & 63, k = q >> 3, t = q & 7;
            float v;
            if (tid < 64) v = sS[k * 16 + t] + sS[(8 + k) * 16 + 8 + t];
            else          v = sS[k * 16 + 8 + t] - sS[(8 + k) * 16 + t];
            g_EF[(size_t)b * 128 + tid] = v;
        }

        const float* Hb = H + (size_t)b * 1024;
        for (int e = tid; e < 1024; e += 256) {
            int c = e >> 7, k = e & 127;
            g_HGT[(size_t)b * 3072 + e] = Hb[k * 8 + c];
        }
    }

    // G^T[i][krow] for krow in [half*64, half*64+64) via 3xTF32 mma
    {
        const int lane = tid & 31, w = tid >> 5;
        const int arow = lane >> 2, acol = lane & 3;
        float cg[4] = {};
        for (int lc = 0; lc < 9; lc++) {
            if (lc + 1 < 9) {
                uint32_t off = (uint32_t)(((lc + 1) & 1) * (64 * 20)) * 4;
                int l0n = (lc + 1) * 16;
                int row = tid >> 2, seg = tid & 3;
                cp16(chBase + off + (uint32_t)(row * 20 + seg * 4) * 4,
                     YYpb + row * LT + l0n + seg * 4);
                CP_COMMIT();
                CP_WAIT1();
            } else {
                CP_WAIT0();
            }
            __syncthreads();
            const float* Ch = sCh2[lc & 1];
            #pragma unroll
            for (int ks = 0; ks < 2; ks++) {
                const int kg = lc * 16 + ks * 8 + acol;
                float av0 = sUtXT[kg * 16 + arow];
                float av1 = sUtXT[kg * 16 + arow + 8];
                float av2 = sUtXT[(kg + 4) * 16 + arow];
                float av3 = sUtXT[(kg + 4) * 16 + arow + 8];
                uint32_t ah[4] = {f2tf(av0), f2tf(av1), f2tf(av2), f2tf(av3)};
                uint32_t al[4] = {f2tf(av0 - __uint_as_float(ah[0])),
                                  f2tf(av1 - __uint_as_float(ah[1])),
                                  f2tf(av2 - __uint_as_float(ah[2])),
                                  f2tf(av3 - __uint_as_float(ah[3]))};
                const int n = w * 8 + arow;
                float bv0 = Ch[n * 20 + ks * 8 + acol];
                float bv1 = Ch[n * 20 + ks * 8 + acol + 4];
                uint32_t bh[2] = {f2tf(bv0), f2tf(bv1)};
                uint32_t bl[2] = {f2tf(bv0 - __uint_as_float(bh[0])),
                                  f2tf(bv1 - __uint_as_float(bh[1]))};
                mma_tf32(cg, ah, bl);
                mma_tf32(cg, al, bh);
                mma_tf32(cg, ah, bh);
            }
            __syncthreads();
        }
        float* dst = g_HGT + (size_t)b * 3072;
        const int col = half * 64 + w * 8 + (lane & 3) * 2;
        *(float2*)(dst + (8 + arow) * 128 + col) = make_float2(cg[0], cg[1]);
        *(float2*)(dst + (16 + arow) * 128 + col) = make_float2(cg[2], cg[3]);
    }
}

// ================= mega GEMM (3xTF32 precise) =================
__global__ __launch_bounds__(128)
void mega_gemm(const float* __restrict__ P, const float* __restrict__ Q,
               float* __restrict__ Out)
{
    __shared__ float buf[4 * TILE_F];
    const int m0 = blockIdx.x * 64;
    const int q0 = blockIdx.y * 64;
    float c[2][4][4] = {};
    tile_gemm<true>(P + (size_t)m0 * 128, Q + (size_t)q0 * 128, 128, 128, c,
                    buf, buf + 2 * TILE_F);
    __syncthreads();

    const int tid = threadIdx.x;
    const int lane = tid & 31, wid = tid >> 5;
    const int wm = wid & 1, wn = wid >> 1;
    #pragma unroll
    for (int mt = 0; mt < 2; mt++)
        #pragma unroll
        for (int nt = 0; nt < 4; nt++)
            #pragma unroll
            for (int k = 0; k < 4; k++) {
                int p = wm * 32 + mt * 16 + (lane >> 2) + (k >> 1) * 8;
                int q = wn * 32 + nt * 8 + (lane & 3) * 2 + (k & 1);
                buf[p * 68 + q] = c[mt][nt][k];
            }
    __syncthreads();
    #pragma unroll 4
    for (int i = 0; i < 32; i++) {
        int idx = i * 128 + tid;
        int p = idx & 63, q = idx >> 6;
        Out[(size_t)(q0 + q) * 128 + m0 + p] = buf[p * 68 + q];
    }
}

// ================= K3: Hv, D, Hvest, soft-threshold (512 thr) =================
__global__ __launch_bounds__(512)
void k3_kernel(const float* __restrict__ sigma2,
               const float* __restrict__ rUt, const float* __restrict__ iUt,
               const float* __restrict__ tao_p, const float* __restrict__ eps_p)
{
    __shared__ float sTc[24 * 128];
    __shared__ float sEF[128];
    __shared__ float sUt[128];
    __shared__ float sHv[1024];
    __shared__ float sHve[1024];

    const int b = blockIdx.x;
    const int tid = threadIdx.x;
    const float tao = tao_p[0];

    for (int i = tid; i < 3072; i += 512) sTc[i] = g_T[(size_t)b * 3072 + i];
    if (tid < 128) {
        sEF[tid] = g_EF[(size_t)b * 128 + tid];
        sUt[tid] = (tid < 64) ? rUt[tid] : iUt[tid - 64];
    }
    __syncthreads();

    {
        const int r = tid >> 2, c0 = (tid & 3) * 2;
        #pragma unroll
        for (int c = c0; c < c0 + 2; c++) {
            float acc = 0.f;
            if (r < 64) {
                #pragma unroll
                for (int k = 0; k < 8; k++)
                    acc += sTc[k * 128 + r] * sUt[k * 8 + c] - sTc[k * 128 + 64 + r] * sUt[64 + k * 8 + c];
            } else {
                #pragma unroll
                for (int k = 0; k < 8; k++)
                    acc += sTc[k * 128 + r] * sUt[k * 8 + c] + sTc[k * 128 + r - 64] * sUt[64 + k * 8 + c];
            }
            sHv[r * 8 + c] = acc;
        }
    }
    __syncthreads();

    {
        const int r = tid >> 2, t0 = (tid & 3) * 2;
        #pragma unroll
        for (int t = t0; t < t0 + 2; t++) {
            float s = 0.f;
            if (r < 64) {
                #pragma unroll
                for (int k = 0; k < 8; k++)
                    s += sHv[r * 8 + k] * sEF[k * 8 + t] + sHv[(64 + r) * 8 + k] * sEF[64 + k * 8 + t];
                s -= sTc[(8 + t) * 128 + r] + sTc[(16 + t) * 128 + 64 + r];
            } else {
                int r2 = r - 64;
                #pragma unroll
                for (int k = 0; k < 8; k++)
                    s += sHv[r * 8 + k] * sEF[k * 8 + t] - sHv[r2 * 8 + k] * sEF[64 + k * 8 + t];
                s -= sTc[(8 + t) * 128 + r] - sTc[(16 + t) * 128 + r2];
            }
            sHve[r * 8 + t] = sHv[r * 8 + t] - tao * s;
        }
    }
    __syncthreads();

    {
        float thr = tao * eps_p[0] * sigma2[b];
        if (tid < 512) {
            int e = tid;
            float re = sHve[e], im = sHve[e + 512];
            float mag = sqrtf(re * re + im * im);
            float s = fmaxf(mag - thr, 0.f) / mag;
            sHve[e] = re * s;
            sHve[e + 512] = im * s;
        }
    }
    __syncthreads();

    for (int i = tid; i < 1024; i += 512) {
        int c = i >> 7, r = i & 127;
        g_HveT[(size_t)b * 1024 + i] = sHve[r * 8 + c];
    }
}

// ================= K5: H_new, W, WTW, F via mma (512 thr) =================
#define CPAD 136
#define CHK (16 * CPAD)
__global__ __launch_bounds__(512)
void k5_kernel(const float* __restrict__ X, const float* __restrict__ Y,
               const float* __restrict__ lambda_W,
               const float* __restrict__ rUt, const float* __restrict__ iUt,
               const float* __restrict__ factor_p,
               float* __restrict__ out_Hnew, float* __restrict__ out_lamW)
{
    __shared__ float sUc[1024];
    __shared__ float sUt[128];
    __shared__ float sHN[1024];
    __shared__ float sW[128 * 24];
    __shared__ float sWTW[256];
    __shared__ float sX[2048];
    __shared__ float sCh[2][CHK];

    const int b = blockIdx.x;
    const int tid = threadIdx.x;

    const float* Yb = Y + (size_t)b * 128 * LD;
    const uint32_t chBase = smem_to_u32(sCh);
    {
        int row = tid >> 5, seg = tid & 31;
        cp16(chBase + (uint32_t)(row * CPAD + seg * 4) * 4, Yb + row * 128 + seg * 4);
    }
    CP_COMMIT();

    for (int i = tid; i < 1024; i += 512) sUc[i] = g_UrHvT[(size_t)b * 1024 + i];
    {
        const float* Xb = X + (size_t)b * 16 * LD;
        for (int e = tid; e < 2048; e += 512) sX[e] = Xb[e];
    }
    if (tid < 128) sUt[tid] = (tid < 64) ? rUt[tid] : iUt[tid - 64];
    __syncthreads();

    {
        const int r = tid >> 2, c0 = (tid & 3) * 2;
        #pragma unroll
        for (int c = c0; c < c0 + 2; c++) {
            float acc = 0.f;
            if (r < 64) {
                #pragma unroll
                for (int k = 0; k < 8; k++)
                    acc += sUc[k * 128 + r] * sUt[c * 8 + k] + sUc[k * 128 + 64 + r] * sUt[64 + c * 8 + k];
            } else {
                #pragma unroll
                for (int k = 0; k < 8; k++)
                    acc += sUc[k * 128 + r] * sUt[c * 8 + k] - sUc[k * 128 + r - 64] * sUt[64 + c * 8 + k];
            }
            sHN[r * 8 + c] = acc;
            out_Hnew[(size_t)b * 1024 + r * 8 + c] = acc;
        }
    }
    __syncthreads();

    for (int e = tid; e < 2048; e += 512) {
        int r = e >> 4, i = e & 15;
        float v;
        if (r < 64) v = (i < 8) ? sHN[r * 8 + i] : -sHN[(64 + r) * 8 + (i - 8)];
        else        v = (i < 8) ? sHN[r * 8 + i] : sHN[(r - 64) * 8 + (i - 8)];
        sW[r * 24 + i] = v;
    }
    __syncthreads();

    if (tid < 256) {
        int i = tid >> 4, j = tid & 15;
        float acc = 0.f;
        #pragma unroll 4
        for (int r = 0; r < 128; r++) acc += sW[r * 24 + i] * sW[r * 24 + j];
        sWTW[tid] = acc;
    }
    __syncthreads();

    {
        const int lane = tid & 31, w = tid >> 5;
        const int arow = lane >> 2, acol = lane & 3;
        float cf[4] = {};
        for (int rc = 0; rc < 8; rc++) {
            if (rc + 1 < 8) {
                uint32_t off = (uint32_t)(((rc + 1) & 1) * CHK) * 4;
                const float* src = Yb + (rc + 1) * 16 * 128;
                int row = tid >> 5, seg = tid & 31;
                cp16(chBase + off + (uint32_t)(row * CPAD + seg * 4) * 4,
                     src + row * 128 + seg * 4);
                CP_COMMIT();
                CP_WAIT1();
            } else {
                CP_WAIT0();
            }
            __syncthreads();
            const float* Ch = sCh[rc & 1];
            #pragma unroll
            for (int ks = 0; ks < 2; ks++) {
                const int kg = rc * 16 + ks * 8 + acol;
                float av0 = sW[kg * 24 + arow];
                float av1 = sW[kg * 24 + arow + 8];
                float av2 = sW[(kg + 4) * 24 + arow];
                float av3 = sW[(kg + 4) * 24 + arow + 8];
                uint32_t ah[4] = {f2tf(av0), f2tf(av1), f2tf(av2), f2tf(av3)};
                uint32_t al[4] = {f2tf(av0 - __uint_as_float(ah[0])),
                                  f2tf(av1 - __uint_as_float(ah[1])),
                                  f2tf(av2 - __uint_as_float(ah[2])),
                                  f2tf(av3 - __uint_as_float(ah[3]))};
                const int n = w * 8 + arow;
                float bv0 = Ch[(ks * 8 + acol) * CPAD + n];
                float bv1 = Ch[(ks * 8 + acol + 4) * CPAD + n];
                uint32_t bh[2] = {f2tf(bv0), f2tf(bv1)};
                uint32_t bl[2] = {f2tf(bv0 - __uint_as_float(bh[0])),
                                  f2tf(bv1 - __uint_as_float(bh[1]))};
                mma_tf32(cf, ah, bl);
                mma_tf32(cf, al, bh);
                mma_tf32(cf, ah, bh);
            }
            __syncthreads();
        }

        float lamW = factor_p[0] * lambda_W[b];
        float* Fb = g_F + (size_t)b * NN;
        float wt0[16], wt1[16];
        #pragma unroll
        for (int j = 0; j < 16; j++) {
            wt0[j] = sWTW[arow * 16 + j];
            wt1[j] = sWTW[(arow + 8) * 16 + j];
        }
        #pragma unroll
        for (int ls = 0; ls < 2; ls++) {
            const int l = w * 8 + (lane & 3) * 2 + ls;
            float xi[16];
            #pragma unroll
            for (int j = 0; j < 16; j++) xi[j] = sX[j * 128 + l];
            float v0 = cf[ls] + lamW * xi[arow];
            float v1 = cf[2 + ls] + lamW * xi[arow + 8];
            #pragma unroll
            for (int j = 0; j < 16; j++) {
                v0 -= wt0[j] * xi[j];
                v1 -= wt1[j] * xi[j];
            }
            *(float2*)(Fb + l * 16 + arow * 2) =
                make_float2(2.f * lamW - 2.f * SQ2F * v0,
                            2.f * lamW - 2.f * SQ2F * v1);
        }
        if (tid == 0) out_lamW[b] = lamW;
    }
}

// ================= split-K MMA GEMM1: partial C[b,n] =================
__global__ __launch_bounds__(128)
void mma_gemm1(float* __restrict__ dummy)
{
    __shared__ float sP[2 * TILE_F];
    __shared__ float sQ[2 * TILE_F];
    const int n0 = blockIdx.x * 64, b0 = blockIdx.y * 64, kh = blockIdx.z;
    float c[2][4][4] = {};
    tile_gemm<false>(g_Vs + (size_t)b0 * MM + kh * 512,
                     g_AT + (size_t)n0 * MM + kh * 512, MM, 512, c, sP, sQ);

    float* Cp = g_C1 + (size_t)kh * BSZ * NN;
    const int lane = threadIdx.x & 31, wid = threadIdx.x >> 5;
    const int wm = wid & 1, wn = wid >> 1;
    #pragma unroll
    for (int mt = 0; mt < 2; mt++)
        #pragma unroll
        for (int rr = 0; rr < 2; rr++) {
            const int b = b0 + wm * 32 + mt * 16 + (lane >> 2) + rr * 8;
            float* Cb = Cp + (size_t)b * NN;
            #pragma unroll
            for (int nt = 0; nt < 4; nt++) {
                const int n = n0 + wn * 32 + nt * 8 + (lane & 3) * 2;
                *(float2*)(Cb + n) = make_float2(c[mt][nt][rr * 2 + 0],
                                                 c[mt][nt][rr * 2 + 1]);
            }
        }
    (void)dummy;
}

// ================= epi1: combine partials -> u_new =================
__global__ void epi1_kernel(const float* __restrict__ La, const float* __restrict__ lamWv,
                            const float* __restrict__ rho_p, const float* __restrict__ kappa_p,
                            float* __restrict__ out_u)
{
    int idx = blockIdx.x * blockDim.x + threadIdx.x;
    if (idx >= BSZ * NN / 4) return;
    float4 p0 = ((const float4*)g_C1)[idx];
    float4 p1 = ((const float4*)(g_C1 + (size_t)BSZ * NN))[idx];
    int e4 = idx * 4;
    int b = e4 >> 11, n = e4 & 2047;
    float rho = rho_p[0], kappa = kappa_p[0];
    float lamW = lamWv[b];
    float den = 4.f * lamW - 2.f * kappa;
    float4 fb = ((const float4*)g_F)[idx];
    float4 la = *(const float4*)(La + n);
    float4 u;
    u.x = fminf(fmaxf((rho * (p0.x + p1.x) + fb.x - kappa) / (rho * la.x + den), 0.f), 1.f);
    u.y = fminf(fmaxf((rho * (p0.y + p1.y) + fb.y - kappa) / (rho * la.y + den), 0.f), 1.f);
    u.z = fminf(fmaxf((rho * (p0.z + p1.z) + fb.z - kappa) / (rho * la.z + den), 0.f), 1.f);
    u.w = fminf(fmaxf((rho * (p0.w + p1.w) + fb.w - kappa) / (rho * la.w + den), 0.f), 1.f);
    ((float4*)out_u)[idx] = u;
}

// ================= split-K MMA GEMM2: partial C[b,m] =================
__global__ __launch_bounds__(128)
void mma_gemm2(const float* __restrict__ A, const float* __restrict__ u_in)
{
    __shared__ float sP[2 * TILE_F];
    __shared__ float sQ[2 * TILE_F];
    const int m0 = blockIdx.x * 64, b0 = blockIdx.y * 64, kh = blockIdx.z;
    float c[2][4][4] = {};
    tile_gemm<false>(u_in + (size_t)b0 * NN + kh * 1024,
                     A + (size_t)m0 * NN + kh * 1024, NN, 1024, c, sP, sQ);

    float* Cp = g_C2 + (size_t)kh * BSZ * MM;
    const int lane = threadIdx.x & 31, wid = threadIdx.x >> 5;
    const int wm = wid & 1, wn = wid >> 1;
    #pragma unroll
    for (int mt = 0; mt < 2; mt++)
        #pragma unroll
        for (int rr = 0; rr < 2; rr++) {
            const int b = b0 + wm * 32 + mt * 16 + (lane >> 2) + rr * 8;
            float* Cb = Cp + (size_t)b * MM;
            #pragma unroll
            for (int nt = 0; nt < 4; nt++) {
                const int m = m0 + wn * 32 + nt * 8 + (lane & 3) * 2;
                *(float2*)(Cb + m) = make_float2(c[mt][nt][rr * 2 + 0],
                                                 c[mt][nt][rr * 2 + 1]);
            }
        }
}

// ================= epi2: combine partials -> z_new, lambda1_new =================
__global__ void epi2_kernel(const float* __restrict__ theta, const float* __restrict__ z_old,
                            const float* __restrict__ l1_old, const float* __restrict__ relax_p,
                            const float* __restrict__ acc_p,
                            float* __restrict__ out_z, float* __restrict__ out_l1)
{
    int idx = blockIdx.x * blockDim.x + threadIdx.x;
    if (idx >= BSZ * MM / 4) return;
    float4 p0 = ((const float4*)g_C2)[idx];
    float4 p1 = ((const float4*)(g_C2 + (size_t)BSZ * MM))[idx];
    int e4 = idx * 4;
    int m = e4 & 1023;
    float relax = relax_p[0], acc = acc_p[0];
    float4 th = *(const float4*)(theta + m);
    float4 zo = ((const float4*)z_old)[idx];
    float4 lo = ((const float4*)l1_old)[idx];
    float4 zn, ln;
    #define DO(comp) { \
        float ct = p0.comp + p1.comp; \
        float zt = th.comp - relax * ct - (1.f - relax) * (th.comp - zo.comp) - lo.comp; \
        float z1 = fmaxf(zt, 0.f); \
        float l1v = z1 - zt; \
        zn.comp = z1 + acc * (z1 - zo.comp); \
        ln.comp = l1v + acc * (l1v - lo.comp); }
    DO(x) DO(y) DO(z) DO(w)
    #undef DO
    ((float4*)out_z)[idx] = zn;
    ((float4*)out_l1)[idx] = ln;
}

// ================= xk: u -> X_new / XXp_new (smem transpose, coalesced) =================
__global__ __launch_bounds__(256)
void xk_kernel(const float* __restrict__ u_new, const float* __restrict__ rXp,
               const float* __restrict__ iXp,
               float* __restrict__ out_X, float* __restrict__ out_XXp)
{
    __shared__ float st[16 * 132];
    const int b = blockIdx.x;
    const int tid = threadIdx.x;
    const float* ub = u_new + (size_t)b * NN;
    for (int n = tid; n < 2048; n += 256) {
        float uv = ub[n];
        int l = n >> 4, t = (n >> 1) & 7, ci = n & 1;
        st[(ci * 8 + t) * 132 + l] = (1.f - 2.f * uv) * INV_SQ2F;
    }
    __syncthreads();
    float* Xb = out_X + (size_t)b * 2048;
    float* XXb = out_XXp + (size_t)b * 2304;
    for (int e = tid; e < 2048; e += 256) {
        int row = e >> 7, l = e & 127;
        float v = st[row * 132 + l];
        Xb[e] = v;
        XXb[row * 144 + l] = v;
    }
    {
        int e = tid;
        int tt = e >> 5, ci = (e >> 4) & 1, lp = e & 15;
        float v = ci ? iXp[(size_t)b * 128 + tt * 16 + lp]
                     : rXp[(size_t)b * 128 + tt * 16 + lp];
        XXb[(ci * 8 + tt) * 144 + 128 + lp] = v;
    }
}

// ================= launch =================
extern "C" void kernel_launch(void* const* d_in, const int* in_sizes, int n_in,
                              void* d_out, int out_size) {
    (void)in_sizes; (void)n_in; (void)out_size;
    const float* sigma2   = (const float*)d_in[0];
    const float* X        = (const float*)d_in[1];
    const float* XXp      = (const float*)d_in[2];
    const float* Y        = (const float*)d_in[3];
    const float* YYp      = (const float*)d_in[4];
    const float* rXp      = (const float*)d_in[5];
    const float* iXp      = (const float*)d_in[6];
    const float* H        = (const float*)d_in[7];
    const float* lambda_W = (const float*)d_in[8];
    const float* z        = (const float*)d_in[10];
    const float* lambda1  = (const float*)d_in[11];
    const float* acc_new  = (const float*)d_in[12];
    const float* A        = (const float*)d_in[13];
    const float* Lambda_A = (const float*)d_in[14];
    const float* theta    = (const float*)d_in[15];
    const float* rUr      = (const float*)d_in[16];
    const float* iUr      = (const float*)d_in[17];
    const float* rUt      = (const float*)d_in[18];
    const float* iUt      = (const float*)d_in[19];
    const float* rho      = (const float*)d_in[20];
    const float* kappa    = (const float*)d_in[21];
    const float* epsilon  = (const float*)d_in[22];
    const float* tao      = (const float*)d_in[23];
    const float* factor   = (const float*)d_in[24];
    const float* relax    = (const float*)d_in[25];
    const float* acc      = (const float*)d_in[26];

    float* out = (float*)d_out;
    float* out_X    = out;
    float* out_XXp  = out + 1048576;
    float* out_H    = out + 2228224;
    float* out_lamW = out + 2752512;
    float* out_u    = out + 2753024;
    float* out_z    = out + 3801600;
    float* out_l1   = out + 4325888;
    float* out_acc  = out + 4850176;

    float* dg_Ur, *dg_UrT, *dg_HGT, *dg_T, *dg_HveT, *dg_UrHvT;
    cudaGetSymbolAddress((void**)&dg_Ur, g_Ur);
    cudaGetSymbolAddress((void**)&dg_UrT, g_UrT);
    cudaGetSymbolAddress((void**)&dg_HGT, g_HGT);
    cudaGetSymbolAddress((void**)&dg_T, g_T);
    cudaGetSymbolAddress((void**)&dg_HveT, g_HveT);
    cudaGetSymbolAddress((void**)&dg_UrHvT, g_UrHvT);

    prep_kernel<<<4161, 256>>>(rUr, iUr, theta, z, lambda1, A, acc_new, out_acc);
    k1a_kernel<<<BSZ * 2, 256>>>(XXp, YYp, H, rUt, iUt);
    mega_gemm<<<dim3(2, BSZ * 24 / 64), 128>>>(dg_UrT, dg_HGT, dg_T);
    k3_kernel<<<BSZ, 512>>>(sigma2, rUt, iUt, tao, epsilon);
    mega_gemm<<<dim3(2, BSZ * 8 / 64), 128>>>(dg_Ur, dg_HveT, dg_UrHvT);
    k5_kernel<<<BSZ, 512>>>(X, Y, lambda_W, rUt, iUt, factor, out_H, out_lamW);
    mma_gemm1<<<dim3(NN / 64, BSZ / 64, 2), 128>>>(nullptr);
    epi1_kernel<<<(BSZ * NN / 4 + 255) / 256, 256>>>(Lambda_A, out_lamW, rho, kappa, out_u);
    mma_gemm2<<<dim3(MM / 64, BSZ / 64, 2), 128>>>(A, out_u);
    epi2_kernel<<<(BSZ * MM / 4 + 255) / 256, 256>>>(theta, z, lambda1, relax, acc,
                                                     out_z, out_l1);
    xk_kernel<<<BSZ, 256>>>(out_u, rXp, iXp, out_X, out_XXp);
}

// round 14
// speedup vs baseline: 1.0512x; 1.0403x over previous
#include <cuda_runtime.h>
#include <cuda_bf16.h>
#include <math.h>
#include <stdint.h>

// Problem constants
#define NR 64
#define NT 8
#define LD 128
#define LP 16
#define LT 144          // LD + LP
#define BSZ 512
#define MM 1024
#define NN 2048         // LDPC_N

#define SQ2F 1.41421356237309504880f
#define INV_SQ2F 0.70710678118654752440f

// -------- scratch (device globals; no runtime allocation) --------
__device__ float g_Ur[128 * 128];
__device__ float g_UrT[128 * 128];
__device__ float g_F[BSZ * NN];       // fbres permuted: [b][n]
__device__ float g_Vs[BSZ * MM];      // theta - z - lambda1
__device__ float g_AT[NN * MM];       // A^T
__device__ float g_HGT[BSZ * 24 * 128];
__device__ float g_T[BSZ * 24 * 128];
__device__ float g_EF[BSZ * 128];
__device__ float g_HveT[BSZ * 8 * 128];
__device__ float g_UrHvT[BSZ * 8 * 128];
__device__ float g_C1[2 * BSZ * NN];  // split-K partials for gemm1
__device__ float g_C2[4 * BSZ * MM];  // split-K partials for gemm2

// ================= mma.sync helpers =================
__device__ __forceinline__ uint32_t smem_to_u32(const void* smem_ptr) {
    uint32_t addr;
    asm("{ .reg .u64 tmp; cvta.to.shared.u64 tmp, %1; cvt.u32.u64 %0, tmp; }"
        : "=r"(addr) : "l"(smem_ptr));
    return addr;
}

__device__ __forceinline__ void cp16(uint32_t s, const float* g) {
    asm volatile("cp.async.cg.shared.global [%0], [%1], 16;" :: "r"(s), "l"(g) : "memory");
}
#define CP_COMMIT() asm volatile("cp.async.commit_group;" ::: "memory")
#define CP_WAIT1()  asm volatile("cp.async.wait_group 1;" ::: "memory")
#define CP_WAIT0()  asm volatile("cp.async.wait_group 0;" ::: "memory")

__device__ __forceinline__ uint32_t f2tf(float f) {
    uint32_t r;
    asm("cvt.rna.tf32.f32 %0, %1;" : "=r"(r) : "f"(f));
    return r;
}

__device__ __forceinline__ void mma_tf32(float* c, const uint32_t* a, const uint32_t* b) {
    asm volatile(
        "mma.sync.aligned.m16n8k8.row.col.f32.tf32.tf32.f32 "
        "{%0,%1,%2,%3}, {%4,%5,%6,%7}, {%8,%9}, {%0,%1,%2,%3};"
        : "+f"(c[0]), "+f"(c[1]), "+f"(c[2]), "+f"(c[3])
        : "r"(a[0]), "r"(a[1]), "r"(a[2]), "r"(a[3]), "r"(b[0]), "r"(b[1]));
}

// ---- shared tile mainloop: C[64x64] += P[64,klen] * Q[64,klen]^T, row stride ld ----
#define TILE_F (64 * 20)
template<bool PRECISE>
__device__ __forceinline__ void tile_gemm(const float* __restrict__ Pg0,
                                          const float* __restrict__ Qg0,
                                          int ld, int klen, float c[2][4][4],
                                          float* sP, float* sQ)
{
    const int tid = threadIdx.x;
    const int lane = tid & 31, wid = tid >> 5;
    const int wm = wid & 1, wn = wid >> 1;
    const int lrow = tid >> 2, lquad = tid & 3;

    uint32_t sPb = smem_to_u32(sP), sQb = smem_to_u32(sQ);
    const int NK = klen >> 4;
    const float* Pg = Pg0 + (size_t)lrow * ld + lquad * 4;
    const float* Qg = Qg0 + (size_t)lrow * ld + lquad * 4;
    const uint32_t spA0 = sPb + (uint32_t)(lrow * 20 + lquad * 4) * 4;
    const uint32_t spA1 = sPb + (uint32_t)((lrow + 32) * 20 + lquad * 4) * 4;
    const uint32_t sqA0 = sQb + (uint32_t)(lrow * 20 + lquad * 4) * 4;
    const uint32_t sqA1 = sQb + (uint32_t)((lrow + 32) * 20 + lquad * 4) * 4;

    {
        const float* p = Pg;  const float* q = Qg;
        cp16(spA0, p); cp16(spA1, p + (size_t)32 * ld);
        cp16(sqA0, q); cp16(sqA1, q + (size_t)32 * ld);
        CP_COMMIT();
        p = Pg + 16; q = Qg + 16;
        uint32_t off = TILE_F * 4;
        cp16(spA0 + off, p); cp16(spA1 + off, p + (size_t)32 * ld);
        cp16(sqA0 + off, q); cp16(sqA1 + off, q + (size_t)32 * ld);
        CP_COMMIT();
    }

    const int arow = lane >> 2, acol = lane & 3;
    for (int kt = 0; kt < NK; kt++) {
        CP_WAIT1();
        __syncthreads();
        const float* Pbuf = sP + (kt & 1) * TILE_F;
        const float* Qbuf = sQ + (kt & 1) * TILE_F;
        #pragma unroll
        for (int ks = 0; ks < 2; ks++) {
            const int k0 = ks * 8 + acol;
            uint32_t a[2][4], bq[4][2];
            uint32_t al[2][4], bl[4][2];
            #pragma unroll
            for (int mt = 0; mt < 2; mt++) {
                const int m = wm * 32 + mt * 16 + arow;
                float v0 = Pbuf[m * 20 + k0];
                float v1 = Pbuf[(m + 8) * 20 + k0];
                float v2 = Pbuf[m * 20 + k0 + 4];
                float v3 = Pbuf[(m + 8) * 20 + k0 + 4];
                a[mt][0] = f2tf(v0); a[mt][1] = f2tf(v1);
                a[mt][2] = f2tf(v2); a[mt][3] = f2tf(v3);
                if (PRECISE) {
                    al[mt][0] = f2tf(v0 - __uint_as_float(a[mt][0]));
                    al[mt][1] = f2tf(v1 - __uint_as_float(a[mt][1]));
                    al[mt][2] = f2tf(v2 - __uint_as_float(a[mt][2]));
                    al[mt][3] = f2tf(v3 - __uint_as_float(a[mt][3]));
                }
            }
            #pragma unroll
            for (int nt = 0; nt < 4; nt++) {
                const int n = wn * 32 + nt * 8 + arow;
                float w0 = Qbuf[n * 20 + k0];
                float w1 = Qbuf[n * 20 + k0 + 4];
                bq[nt][0] = f2tf(w0); bq[nt][1] = f2tf(w1);
                if (PRECISE) {
                    bl[nt][0] = f2tf(w0 - __uint_as_float(bq[nt][0]));
                    bl[nt][1] = f2tf(w1 - __uint_as_float(bq[nt][1]));
                }
            }
            #pragma unroll
            for (int mt = 0; mt < 2; mt++)
                #pragma unroll
                for (int nt = 0; nt < 4; nt++) {
                    if (PRECISE) {
                        mma_tf32(c[mt][nt], a[mt], bl[nt]);
                        mma_tf32(c[mt][nt], al[mt], bq[nt]);
                    }
                    mma_tf32(c[mt][nt], a[mt], bq[nt]);
                }
        }
        __syncthreads();
        if (kt + 2 < NK) {
            uint32_t off = (uint32_t)((kt & 1) * TILE_F) * 4;
            const float* p = Pg + (kt + 2) * 16;
            const float* q = Qg + (kt + 2) * 16;
            cp16(spA0 + off, p); cp16(spA1 + off, p + (size_t)32 * ld);
            cp16(sqA0 + off, q); cp16(sqA1 + off, q + (size_t)32 * ld);
        }
        CP_COMMIT();
    }
    CP_WAIT0();
}

// ================= prep: Ur/UrT + Vs + AT + acc =================
__global__ __launch_bounds__(256)
void prep_kernel(const float* __restrict__ rUr, const float* __restrict__ iUr,
                 const float* __restrict__ theta, const float* __restrict__ z,
                 const float* __restrict__ l1, const float* __restrict__ A,
                 const float* __restrict__ accnew_in, float* __restrict__ out_acc)
{
    __shared__ float t[32][33];
    const int bi = blockIdx.x;
    const int tid = threadIdx.x;

    if (bi < 64) {
        int e = bi * 256 + tid;
        int i = e >> 7, j = e & 127;
        float v, vt;
        if (i < 64) v = (j < 64) ? rUr[i * 64 + j] : -iUr[i * 64 + (j - 64)];
        else        v = (j < 64) ? iUr[(i - 64) * 64 + j] : rUr[(i - 64) * 64 + (j - 64)];
        g_Ur[e] = v;
        if (i < 64) vt = (j < 64) ? rUr[j * 64 + i] : iUr[(j - 64) * 64 + i];
        else        vt = (j < 64) ? -iUr[j * 64 + (i - 64)] : rUr[(j - 64) * 64 + (i - 64)];
        g_UrT[e] = vt;
    } else if (bi < 2112) {
        int e = (bi - 64) * 256 + tid;
        int m = e & (MM - 1);
        g_Vs[e] = theta[m] - z[e] - l1[e];
    } else if (bi < 4160) {
        int idx = bi - 2112;
        int n0 = (idx & 63) * 32, m0 = (idx >> 6) * 32;
        int tx = tid & 31, ty = tid >> 5;
        #pragma unroll
        for (int q = 0; q < 4; q++)
            t[ty + 8 * q][tx] = A[(size_t)(m0 + ty + 8 * q) * NN + n0 + tx];
        __syncthreads();
        #pragma unroll
        for (int q = 0; q < 4; q++)
            g_AT[(size_t)(n0 + ty + 8 * q) * MM + m0 + tx] = t[tx][ty + 8 * q];
    } else {
        if (tid == 0) out_acc[0] = accnew_in[0];
    }
}

// ================= K1a: per-batch front phases, 2 CTAs/batch =================
__global__ __launch_bounds__(256)
void k1a_kernel(const float* __restrict__ XXp, const float* __restrict__ YYp,
                const float* __restrict__ H,
                const float* __restrict__ rUt, const float* __restrict__ iUt)
{
    __shared__ float sXXp[16 * LT];
    __shared__ float sUtXT[LT * 16];
    __shared__ float sS[256];
    __shared__ float sCh2[2][64 * 20];
    __shared__ float sUt[128];

    const int b = blockIdx.x >> 1;
    const int half = blockIdx.x & 1;
    const int tid = threadIdx.x;

    const float* XXpb = XXp + (size_t)b * 16 * LT;
    for (int i = tid; i < 16 * LT; i += 256) sXXp[i] = XXpb[i];
    if (tid < 128) sUt[tid] = (tid < 64) ? rUt[tid] : iUt[tid - 64];

    const float* YYpb = YYp + (size_t)b * 128 * LT + (size_t)half * 64 * LT;
    const uint32_t chBase = smem_to_u32(sCh2);
    {
        int row = tid >> 2, seg = tid & 3;
        cp16(chBase + (uint32_t)(row * 20 + seg * 4) * 4, YYpb + row * LT + seg * 4);
    }
    CP_COMMIT();
    __syncthreads();

    for (int e = tid; e < 16 * LT; e += 256) {
        int i = e & 15, l = e >> 4;
        float acc = 0.f;
        if (i < 8) {
            #pragma unroll
            for (int k = 0; k < 8; k++) {
                acc += sUt[k * 8 + i] * sXXp[k * LT + l];
                acc += sUt[64 + k * 8 + i] * sXXp[(8 + k) * LT + l];
            }
        } else {
            int i2 = i - 8;
            #pragma unroll
            for (int k = 0; k < 8; k++) {
                acc -= sUt[64 + k * 8 + i2] * sXXp[k * LT + l];
                acc += sUt[k * 8 + i2] * sXXp[(8 + k) * LT + l];
            }
        }
        sUtXT[l * 16 + i] = acc;
    }
    __syncthreads();

    if (half == 0) {
        {
            int i = tid >> 4, j = tid & 15;
            float acc = 0.f;
            #pragma unroll 4
            for (int l = 0; l < LT; l++) acc += sUtXT[l * 16 + i] * sUtXT[l * 16 + j];
            sS[tid] = acc;
        }
        __syncthreads();

        if (tid < 128) {
            int q = tid & 63, k = q >> 3, t = q & 7;
            float v;
            if (tid < 64) v = sS[k * 16 + t] + sS[(8 + k) * 16 + 8 + t];
            else          v = sS[k * 16 + 8 + t] - sS[(8 + k) * 16 + t];
            g_EF[(size_t)b * 128 + tid] = v;
        }

        const float* Hb = H + (size_t)b * 1024;
        for (int e = tid; e < 1024; e += 256) {
            int c = e >> 7, k = e & 127;
            g_HGT[(size_t)b * 3072 + e] = Hb[k * 8 + c];
        }
    }

    // G^T[i][krow] for krow in [half*64, half*64+64) via 3xTF32 mma
    {
        const int lane = tid & 31, w = tid >> 5;
        const int arow = lane >> 2, acol = lane & 3;
        float cg[4] = {};
        for (int lc = 0; lc < 9; lc++) {
            if (lc + 1 < 9) {
                uint32_t off = (uint32_t)(((lc + 1) & 1) * (64 * 20)) * 4;
                int l0n = (lc + 1) * 16;
                int row = tid >> 2, seg = tid & 3;
                cp16(chBase + off + (uint32_t)(row * 20 + seg * 4) * 4,
                     YYpb + row * LT + l0n + seg * 4);
                CP_COMMIT();
                CP_WAIT1();
            } else {
                CP_WAIT0();
            }
            __syncthreads();
            const float* Ch = sCh2[lc & 1];
            #pragma unroll
            for (int ks = 0; ks < 2; ks++) {
                const int kg = lc * 16 + ks * 8 + acol;
                float av0 = sUtXT[kg * 16 + arow];
                float av1 = sUtXT[kg * 16 + arow + 8];
                float av2 = sUtXT[(kg + 4) * 16 + arow];
                float av3 = sUtXT[(kg + 4) * 16 + arow + 8];
                uint32_t ah[4] = {f2tf(av0), f2tf(av1), f2tf(av2), f2tf(av3)};
                uint32_t al[4] = {f2tf(av0 - __uint_as_float(ah[0])),
                                  f2tf(av1 - __uint_as_float(ah[1])),
                                  f2tf(av2 - __uint_as_float(ah[2])),
                                  f2tf(av3 - __uint_as_float(ah[3]))};
                const int n = w * 8 + arow;
                float bv0 = Ch[n * 20 + ks * 8 + acol];
                float bv1 = Ch[n * 20 + ks * 8 + acol + 4];
                uint32_t bh[2] = {f2tf(bv0), f2tf(bv1)};
                uint32_t bl[2] = {f2tf(bv0 - __uint_as_float(bh[0])),
                                  f2tf(bv1 - __uint_as_float(bh[1]))};
                mma_tf32(cg, ah, bl);
                mma_tf32(cg, al, bh);
                mma_tf32(cg, ah, bh);
            }
            __syncthreads();
        }
        float* dst = g_HGT + (size_t)b * 3072;
        const int col = half * 64 + w * 8 + (lane & 3) * 2;
        *(float2*)(dst + (8 + arow) * 128 + col) = make_float2(cg[0], cg[1]);
        *(float2*)(dst + (16 + arow) * 128 + col) = make_float2(cg[2], cg[3]);
    }
}

// ================= mega GEMM (3xTF32 precise) =================
__global__ __launch_bounds__(128)
void mega_gemm(const float* __restrict__ P, const float* __restrict__ Q,
               float* __restrict__ Out)
{
    __shared__ float buf[4 * TILE_F];
    const int m0 = blockIdx.x * 64;
    const int q0 = blockIdx.y * 64;
    float c[2][4][4] = {};
    tile_gemm<true>(P + (size_t)m0 * 128, Q + (size_t)q0 * 128, 128, 128, c,
                    buf, buf + 2 * TILE_F);
    __syncthreads();

    const int tid = threadIdx.x;
    const int lane = tid & 31, wid = tid >> 5;
    const int wm = wid & 1, wn = wid >> 1;
    #pragma unroll
    for (int mt = 0; mt < 2; mt++)
        #pragma unroll
        for (int nt = 0; nt < 4; nt++)
            #pragma unroll
            for (int k = 0; k < 4; k++) {
                int p = wm * 32 + mt * 16 + (lane >> 2) + (k >> 1) * 8;
                int q = wn * 32 + nt * 8 + (lane & 3) * 2 + (k & 1);
                buf[p * 68 + q] = c[mt][nt][k];
            }
    __syncthreads();
    #pragma unroll 4
    for (int i = 0; i < 32; i++) {
        int idx = i * 128 + tid;
        int p = idx & 63, q = idx >> 6;
        Out[(size_t)(q0 + q) * 128 + m0 + p] = buf[p * 68 + q];
    }
}

// ================= K3: Hv, D, Hvest, soft-threshold (512 thr) =================
__global__ __launch_bounds__(512)
void k3_kernel(const float* __restrict__ sigma2,
               const float* __restrict__ rUt, const float* __restrict__ iUt,
               const float* __restrict__ tao_p, const float* __restrict__ eps_p)
{
    __shared__ float sTc[24 * 128];
    __shared__ float sEF[128];
    __shared__ float sUt[128];
    __shared__ float sHv[1024];
    __shared__ float sHve[1024];

    const int b = blockIdx.x;
    const int tid = threadIdx.x;
    const float tao = tao_p[0];

    for (int i = tid; i < 3072; i += 512) sTc[i] = g_T[(size_t)b * 3072 + i];
    if (tid < 128) {
        sEF[tid] = g_EF[(size_t)b * 128 + tid];
        sUt[tid] = (tid < 64) ? rUt[tid] : iUt[tid - 64];
    }
    __syncthreads();

    {
        const int r = tid >> 2, c0 = (tid & 3) * 2;
        #pragma unroll
        for (int c = c0; c < c0 + 2; c++) {
            float acc = 0.f;
            if (r < 64) {
                #pragma unroll
                for (int k = 0; k < 8; k++)
                    acc += sTc[k * 128 + r] * sUt[k * 8 + c] - sTc[k * 128 + 64 + r] * sUt[64 + k * 8 + c];
            } else {
                #pragma unroll
                for (int k = 0; k < 8; k++)
                    acc += sTc[k * 128 + r] * sUt[k * 8 + c] + sTc[k * 128 + r - 64] * sUt[64 + k * 8 + c];
            }
            sHv[r * 8 + c] = acc;
        }
    }
    __syncthreads();

    {
        const int r = tid >> 2, t0 = (tid & 3) * 2;
        #pragma unroll
        for (int t = t0; t < t0 + 2; t++) {
            float s = 0.f;
            if (r < 64) {
                #pragma unroll
                for (int k = 0; k < 8; k++)
                    s += sHv[r * 8 + k] * sEF[k * 8 + t] + sHv[(64 + r) * 8 + k] * sEF[64 + k * 8 + t];
                s -= sTc[(8 + t) * 128 + r] + sTc[(16 + t) * 128 + 64 + r];
            } else {
                int r2 = r - 64;
                #pragma unroll
                for (int k = 0; k < 8; k++)
                    s += sHv[r * 8 + k] * sEF[k * 8 + t] - sHv[r2 * 8 + k] * sEF[64 + k * 8 + t];
                s -= sTc[(8 + t) * 128 + r] - sTc[(16 + t) * 128 + r2];
            }
            sHve[r * 8 + t] = sHv[r * 8 + t] - tao * s;
        }
    }
    __syncthreads();

    {
        float thr = tao * eps_p[0] * sigma2[b];
        if (tid < 512) {
            int e = tid;
            float re = sHve[e], im = sHve[e + 512];
            float mag = sqrtf(re * re + im * im);
            float s = fmaxf(mag - thr, 0.f) / mag;
            sHve[e] = re * s;
            sHve[e + 512] = im * s;
        }
    }
    __syncthreads();

    for (int i = tid; i < 1024; i += 512) {
        int c = i >> 7, r = i & 127;
        g_HveT[(size_t)b * 1024 + i] = sHve[r * 8 + c];
    }
}

// ================= K5: H_new, W, WTW, F via mma (512 thr) =================
#define CPAD 136
#define CHK (16 * CPAD)
__global__ __launch_bounds__(512)
void k5_kernel(const float* __restrict__ X, const float* __restrict__ Y,
               const float* __restrict__ lambda_W,
               const float* __restrict__ rUt, const float* __restrict__ iUt,
               const float* __restrict__ factor_p,
               float* __restrict__ out_Hnew, float* __restrict__ out_lamW)
{
    __shared__ float sUc[1024];
    __shared__ float sUt[128];
    __shared__ float sHN[1024];
    __shared__ float sW[128 * 24];
    __shared__ float sWTW[256];
    __shared__ float sX[2048];
    __shared__ float sCh[2][CHK];

    const int b = blockIdx.x;
    const int tid = threadIdx.x;

    const float* Yb = Y + (size_t)b * 128 * LD;
    const uint32_t chBase = smem_to_u32(sCh);
    {
        int row = tid >> 5, seg = tid & 31;
        cp16(chBase + (uint32_t)(row * CPAD + seg * 4) * 4, Yb + row * 128 + seg * 4);
    }
    CP_COMMIT();

    for (int i = tid; i < 1024; i += 512) sUc[i] = g_UrHvT[(size_t)b * 1024 + i];
    {
        const float* Xb = X + (size_t)b * 16 * LD;
        for (int e = tid; e < 2048; e += 512) sX[e] = Xb[e];
    }
    if (tid < 128) sUt[tid] = (tid < 64) ? rUt[tid] : iUt[tid - 64];
    __syncthreads();

    {
        const int r = tid >> 2, c0 = (tid & 3) * 2;
        #pragma unroll
        for (int c = c0; c < c0 + 2; c++) {
            float acc = 0.f;
            if (r < 64) {
                #pragma unroll
                for (int k = 0; k < 8; k++)
                    acc += sUc[k * 128 + r] * sUt[c * 8 + k] + sUc[k * 128 + 64 + r] * sUt[64 + c * 8 + k];
            } else {
                #pragma unroll
                for (int k = 0; k < 8; k++)
                    acc += sUc[k * 128 + r] * sUt[c * 8 + k] - sUc[k * 128 + r - 64] * sUt[64 + c * 8 + k];
            }
            sHN[r * 8 + c] = acc;
            out_Hnew[(size_t)b * 1024 + r * 8 + c] = acc;
        }
    }
    __syncthreads();

    for (int e = tid; e < 2048; e += 512) {
        int r = e >> 4, i = e & 15;
        float v;
        if (r < 64) v = (i < 8) ? sHN[r * 8 + i] : -sHN[(64 + r) * 8 + (i - 8)];
        else        v = (i < 8) ? sHN[r * 8 + i] : sHN[(r - 64) * 8 + (i - 8)];
        sW[r * 24 + i] = v;
    }
    __syncthreads();

    if (tid < 256) {
        int i = tid >> 4, j = tid & 15;
        float acc = 0.f;
        #pragma unroll 4
        for (int r = 0; r < 128; r++) acc += sW[r * 24 + i] * sW[r * 24 + j];
        sWTW[tid] = acc;
    }
    __syncthreads();

    {
        const int lane = tid & 31, w = tid >> 5;
        const int arow = lane >> 2, acol = lane & 3;
        float cf[4] = {};
        for (int rc = 0; rc < 8; rc++) {
            if (rc + 1 < 8) {
                uint32_t off = (uint32_t)(((rc + 1) & 1) * CHK) * 4;
                const float* src = Yb + (rc + 1) * 16 * 128;
                int row = tid >> 5, seg = tid & 31;
                cp16(chBase + off + (uint32_t)(row * CPAD + seg * 4) * 4,
                     src + row * 128 + seg * 4);
                CP_COMMIT();
                CP_WAIT1();
            } else {
                CP_WAIT0();
            }
            __syncthreads();
            const float* Ch = sCh[rc & 1];
            #pragma unroll
            for (int ks = 0; ks < 2; ks++) {
                const int kg = rc * 16 + ks * 8 + acol;
                float av0 = sW[kg * 24 + arow];
                float av1 = sW[kg * 24 + arow + 8];
                float av2 = sW[(kg + 4) * 24 + arow];
                float av3 = sW[(kg + 4) * 24 + arow + 8];
                uint32_t ah[4] = {f2tf(av0), f2tf(av1), f2tf(av2), f2tf(av3)};
                uint32_t al[4] = {f2tf(av0 - __uint_as_float(ah[0])),
                                  f2tf(av1 - __uint_as_float(ah[1])),
                                  f2tf(av2 - __uint_as_float(ah[2])),
                                  f2tf(av3 - __uint_as_float(ah[3]))};
                const int n = w * 8 + arow;
                float bv0 = Ch[(ks * 8 + acol) * CPAD + n];
                float bv1 = Ch[(ks * 8 + acol + 4) * CPAD + n];
                uint32_t bh[2] = {f2tf(bv0), f2tf(bv1)};
                uint32_t bl[2] = {f2tf(bv0 - __uint_as_float(bh[0])),
                                  f2tf(bv1 - __uint_as_float(bh[1]))};
                mma_tf32(cf, ah, bl);
                mma_tf32(cf, al, bh);
                mma_tf32(cf, ah, bh);
            }
            __syncthreads();
        }

        float lamW = factor_p[0] * lambda_W[b];
        float* Fb = g_F + (size_t)b * NN;
        float wt0[16], wt1[16];
        #pragma unroll
        for (int j = 0; j < 16; j++) {
            wt0[j] = sWTW[arow * 16 + j];
            wt1[j] = sWTW[(arow + 8) * 16 + j];
        }
        #pragma unroll
        for (int ls = 0; ls < 2; ls++) {
            const int l = w * 8 + (lane & 3) * 2 + ls;
            float xi[16];
            #pragma unroll
            for (int j = 0; j < 16; j++) xi[j] = sX[j * 128 + l];
            float v0 = cf[ls] + lamW * xi[arow];
            float v1 = cf[2 + ls] + lamW * xi[arow + 8];
            #pragma unroll
            for (int j = 0; j < 16; j++) {
                v0 -= wt0[j] * xi[j];
                v1 -= wt1[j] * xi[j];
            }
            *(float2*)(Fb + l * 16 + arow * 2) =
                make_float2(2.f * lamW - 2.f * SQ2F * v0,
                            2.f * lamW - 2.f * SQ2F * v1);
        }
        if (tid == 0) out_lamW[b] = lamW;
    }
}

// ================= split-K MMA GEMM1: partial C[b,n] =================
__global__ __launch_bounds__(128)
void mma_gemm1(float* __restrict__ dummy)
{
    __shared__ float sP[2 * TILE_F];
    __shared__ float sQ[2 * TILE_F];
    const int n0 = blockIdx.x * 64, b0 = blockIdx.y * 64, kh = blockIdx.z;
    float c[2][4][4] = {};
    tile_gemm<false>(g_Vs + (size_t)b0 * MM + kh * 512,
                     g_AT + (size_t)n0 * MM + kh * 512, MM, 512, c, sP, sQ);

    float* Cp = g_C1 + (size_t)kh * BSZ * NN;
    const int lane = threadIdx.x & 31, wid = threadIdx.x >> 5;
    const int wm = wid & 1, wn = wid >> 1;
    #pragma unroll
    for (int mt = 0; mt < 2; mt++)
        #pragma unroll
        for (int rr = 0; rr < 2; rr++) {
            const int b = b0 + wm * 32 + mt * 16 + (lane >> 2) + rr * 8;
            float* Cb = Cp + (size_t)b * NN;
            #pragma unroll
            for (int nt = 0; nt < 4; nt++) {
                const int n = n0 + wn * 32 + nt * 8 + (lane & 3) * 2;
                *(float2*)(Cb + n) = make_float2(c[mt][nt][rr * 2 + 0],
                                                 c[mt][nt][rr * 2 + 1]);
            }
        }
    (void)dummy;
}

// ================= epi1x: partials -> u_new + X_new + XXp (per-batch, fused transpose) =================
__global__ __launch_bounds__(512)
void epi1x_kernel(const float* __restrict__ La, const float* __restrict__ lamWv,
                  const float* __restrict__ rho_p, const float* __restrict__ kappa_p,
                  const float* __restrict__ rXp, const float* __restrict__ iXp,
                  float* __restrict__ out_u, float* __restrict__ out_X,
                  float* __restrict__ out_XXp)
{
    __shared__ float st[16 * 132];
    const int b = blockIdx.x;
    const int tid = threadIdx.x;
    const int n0 = tid * 4;
    const size_t base = (size_t)b * NN + n0;

    float4 p0 = *(const float4*)(g_C1 + base);
    float4 p1 = *(const float4*)(g_C1 + (size_t)BSZ * NN + base);
    float4 fb = *(const float4*)(g_F + base);
    float4 la = *(const float4*)(La + n0);
    const float rho = rho_p[0], kappa = kappa_p[0];
    const float lamW = lamWv[b];
    const float den = 4.f * lamW - 2.f * kappa;
    float4 u;
    u.x = fminf(fmaxf((rho * (p0.x + p1.x) + fb.x - kappa) / (rho * la.x + den), 0.f), 1.f);
    u.y = fminf(fmaxf((rho * (p0.y + p1.y) + fb.y - kappa) / (rho * la.y + den), 0.f), 1.f);
    u.z = fminf(fmaxf((rho * (p0.z + p1.z) + fb.z - kappa) / (rho * la.z + den), 0.f), 1.f);
    u.w = fminf(fmaxf((rho * (p0.w + p1.w) + fb.w - kappa) / (rho * la.w + den), 0.f), 1.f);
    *(float4*)(out_u + base) = u;

    // transpose into smem: n = n0+j -> l = n>>4, t = (n>>1)&7, ci = n&1
    {
        const int l = n0 >> 4;
        const int t0 = (n0 >> 1) & 7;
        st[t0 * 132 + l]       = (1.f - 2.f * u.x) * INV_SQ2F;
        st[(8 + t0) * 132 + l] = (1.f - 2.f * u.y) * INV_SQ2F;
        st[(t0 + 1) * 132 + l] = (1.f - 2.f * u.z) * INV_SQ2F;
        st[(9 + t0) * 132 + l] = (1.f - 2.f * u.w) * INV_SQ2F;
    }
    __syncthreads();

    float* Xb = out_X + (size_t)b * 2048;
    float* XXb = out_XXp + (size_t)b * 2304;
    for (int e = tid; e < 2048; e += 512) {
        int row = e >> 7, l = e & 127;
        float v = st[row * 132 + l];
        Xb[e] = v;
        XXb[row * 144 + l] = v;
    }
    if (tid < 256) {
        int e = tid;
        int tt = e >> 5, ci = (e >> 4) & 1, lp = e & 15;
        float v = ci ? iXp[(size_t)b * 128 + tt * 16 + lp]
                     : rXp[(size_t)b * 128 + tt * 16 + lp];
        XXb[(ci * 8 + tt) * 144 + 128 + lp] = v;
    }
}

// ================= split-K(4) MMA GEMM2: partial C[b,m] =================
__global__ __launch_bounds__(128)
void mma_gemm2(const float* __restrict__ A, const float* __restrict__ u_in)
{
    __shared__ float sP[2 * TILE_F];
    __shared__ float sQ[2 * TILE_F];
    const int m0 = blockIdx.x * 64, b0 = blockIdx.y * 64, kh = blockIdx.z;
    float c[2][4][4] = {};
    tile_gemm<false>(u_in + (size_t)b0 * NN + kh * 512,
                     A + (size_t)m0 * NN + kh * 512, NN, 512, c, sP, sQ);

    float* Cp = g_C2 + (size_t)kh * BSZ * MM;
    const int lane = threadIdx.x & 31, wid = threadIdx.x >> 5;
    const int wm = wid & 1, wn = wid >> 1;
    #pragma unroll
    for (int mt = 0; mt < 2; mt++)
        #pragma unroll
        for (int rr = 0; rr < 2; rr++) {
            const int b = b0 + wm * 32 + mt * 16 + (lane >> 2) + rr * 8;
            float* Cb = Cp + (size_t)b * MM;
            #pragma unroll
            for (int nt = 0; nt < 4; nt++) {
                const int m = m0 + wn * 32 + nt * 8 + (lane & 3) * 2;
                *(float2*)(Cb + m) = make_float2(c[mt][nt][rr * 2 + 0],
                                                 c[mt][nt][rr * 2 + 1]);
            }
        }
}

// ================= epi2: combine 4 partials -> z_new, lambda1_new =================
__global__ void epi2_kernel(const float* __restrict__ theta, const float* __restrict__ z_old,
                            const float* __restrict__ l1_old, const float* __restrict__ relax_p,
                            const float* __restrict__ acc_p,
                            float* __restrict__ out_z, float* __restrict__ out_l1)
{
    int idx = blockIdx.x * blockDim.x + threadIdx.x;
    if (idx >= BSZ * MM / 4) return;
    float4 p0 = ((const float4*)g_C2)[idx];
    float4 p1 = ((const float4*)(g_C2 + (size_t)BSZ * MM))[idx];
    float4 p2 = ((const float4*)(g_C2 + (size_t)2 * BSZ * MM))[idx];
    float4 p3 = ((const float4*)(g_C2 + (size_t)3 * BSZ * MM))[idx];
    int e4 = idx * 4;
    int m = e4 & 1023;
    float relax = relax_p[0], acc = acc_p[0];
    float4 th = *(const float4*)(theta + m);
    float4 zo = ((const float4*)z_old)[idx];
    float4 lo = ((const float4*)l1_old)[idx];
    float4 zn, ln;
    #define DO(comp) { \
        float ct = (p0.comp + p1.comp) + (p2.comp + p3.comp); \
        float zt = th.comp - relax * ct - (1.f - relax) * (th.comp - zo.comp) - lo.comp; \
        float z1 = fmaxf(zt, 0.f); \
        float l1v = z1 - zt; \
        zn.comp = z1 + acc * (z1 - zo.comp); \
        ln.comp = l1v + acc * (l1v - lo.comp); }
    DO(x) DO(y) DO(z) DO(w)
    #undef DO
    ((float4*)out_z)[idx] = zn;
    ((float4*)out_l1)[idx] = ln;
}

// ================= launch =================
extern "C" void kernel_launch(void* const* d_in, const int* in_sizes, int n_in,
                              void* d_out, int out_size) {
    (void)in_sizes; (void)n_in; (void)out_size;
    const float* sigma2   = (const float*)d_in[0];
    const float* X        = (const float*)d_in[1];
    const float* XXp      = (const float*)d_in[2];
    const float* Y        = (const float*)d_in[3];
    const float* YYp      = (const float*)d_in[4];
    const float* rXp      = (const float*)d_in[5];
    const float* iXp      = (const float*)d_in[6];
    const float* H        = (const float*)d_in[7];
    const float* lambda_W = (const float*)d_in[8];
    const float* z        = (const float*)d_in[10];
    const float* lambda1  = (const float*)d_in[11];
    const float* acc_new  = (const float*)d_in[12];
    const float* A        = (const float*)d_in[13];
    const float* Lambda_A = (const float*)d_in[14];
    const float* theta    = (const float*)d_in[15];
    const float* rUr      = (const float*)d_in[16];
    const float* iUr      = (const float*)d_in[17];
    const float* rUt      = (const float*)d_in[18];
    const float* iUt      = (const float*)d_in[19];
    const float* rho      = (const float*)d_in[20];
    const float* kappa    = (const float*)d_in[21];
    const float* epsilon  = (const float*)d_in[22];
    const float* tao      = (const float*)d_in[23];
    const float* factor   = (const float*)d_in[24];
    const float* relax    = (const float*)d_in[25];
    const float* acc      = (const float*)d_in[26];

    float* out = (float*)d_out;
    float* out_X    = out;
    float* out_XXp  = out + 1048576;
    float* out_H    = out + 2228224;
    float* out_lamW = out + 2752512;
    float* out_u    = out + 2753024;
    float* out_z    = out + 3801600;
    float* out_l1   = out + 4325888;
    float* out_acc  = out + 4850176;

    float* dg_Ur, *dg_UrT, *dg_HGT, *dg_T, *dg_HveT, *dg_UrHvT;
    cudaGetSymbolAddress((void**)&dg_Ur, g_Ur);
    cudaGetSymbolAddress((void**)&dg_UrT, g_UrT);
    cudaGetSymbolAddress((void**)&dg_HGT, g_HGT);
    cudaGetSymbolAddress((void**)&dg_T, g_T);
    cudaGetSymbolAddress((void**)&dg_HveT, g_HveT);
    cudaGetSymbolAddress((void**)&dg_UrHvT, g_UrHvT);

    prep_kernel<<<4161, 256>>>(rUr, iUr, theta, z, lambda1, A, acc_new, out_acc);
    k1a_kernel<<<BSZ * 2, 256>>>(XXp, YYp, H, rUt, iUt);
    mega_gemm<<<dim3(2, BSZ * 24 / 64), 128>>>(dg_UrT, dg_HGT, dg_T);
    k3_kernel<<<BSZ, 512>>>(sigma2, rUt, iUt, tao, epsilon);
    mega_gemm<<<dim3(2, BSZ * 8 / 64), 128>>>(dg_Ur, dg_HveT, dg_UrHvT);
    k5_kernel<<<BSZ, 512>>>(X, Y, lambda_W, rUt, iUt, factor, out_H, out_lamW);
    mma_gemm1<<<dim3(NN / 64, BSZ / 64, 2), 128>>>(nullptr);
    epi1x_kernel<<<BSZ, 512>>>(Lambda_A, out_lamW, rho, kappa, rXp, iXp,
                               out_u, out_X, out_XXp);
    mma_gemm2<<<dim3(MM / 64, BSZ / 64, 4), 128>>>(A, out_u);
    epi2_kernel<<<(BSZ * MM / 4 + 255) / 256, 256>>>(theta, z, lambda1, relax, acc,
                                                     out_z, out_l1);
}

// round 15
// speedup vs baseline: 1.0945x; 1.0412x over previous
#include <cuda_runtime.h>
#include <cuda_bf16.h>
#include <math.h>
#include <stdint.h>

// Problem constants
#define NR 64
#define NT 8
#define LD 128
#define LP 16
#define LT 144          // LD + LP
#define BSZ 512
#define MM 1024
#define NN 2048         // LDPC_N

#define SQ2F 1.41421356237309504880f
#define INV_SQ2F 0.70710678118654752440f

// -------- scratch (device globals; no runtime allocation) --------
__device__ float g_Ur[128 * 128];
__device__ float g_UrT[128 * 128];
__device__ float g_F[BSZ * NN];       // fbres permuted: [b][n]
__device__ float g_Vs[BSZ * MM];      // theta - z - lambda1
__device__ float g_AT[NN * MM];       // A^T
__device__ float g_HGT[BSZ * 24 * 128];
__device__ float g_T[BSZ * 24 * 128];
__device__ float g_EF[BSZ * 128];
__device__ float g_HveT[BSZ * 8 * 128];
__device__ float g_UrHvT[BSZ * 8 * 128];
__device__ float g_C1[2 * BSZ * NN];  // split-K partials for gemm1
__device__ float g_C2[4 * BSZ * MM];  // split-K partials for gemm2

// ================= mma.sync helpers =================
__device__ __forceinline__ uint32_t smem_to_u32(const void* smem_ptr) {
    uint32_t addr;
    asm("{ .reg .u64 tmp; cvta.to.shared.u64 tmp, %1; cvt.u32.u64 %0, tmp; }"
        : "=r"(addr) : "l"(smem_ptr));
    return addr;
}

__device__ __forceinline__ void cp16(uint32_t s, const float* g) {
    asm volatile("cp.async.cg.shared.global [%0], [%1], 16;" :: "r"(s), "l"(g) : "memory");
}
#define CP_COMMIT() asm volatile("cp.async.commit_group;" ::: "memory")
#define CP_WAIT1()  asm volatile("cp.async.wait_group 1;" ::: "memory")
#define CP_WAIT0()  asm volatile("cp.async.wait_group 0;" ::: "memory")

__device__ __forceinline__ uint32_t f2tf(float f) {
    uint32_t r;
    asm("cvt.rna.tf32.f32 %0, %1;" : "=r"(r) : "f"(f));
    return r;
}

__device__ __forceinline__ void mma_tf32(float* c, const uint32_t* a, const uint32_t* b) {
    asm volatile(
        "mma.sync.aligned.m16n8k8.row.col.f32.tf32.tf32.f32 "
        "{%0,%1,%2,%3}, {%4,%5,%6,%7}, {%8,%9}, {%0,%1,%2,%3};"
        : "+f"(c[0]), "+f"(c[1]), "+f"(c[2]), "+f"(c[3])
        : "r"(a[0]), "r"(a[1]), "r"(a[2]), "r"(a[3]), "r"(b[0]), "r"(b[1]));
}

// ---- shared tile mainloop: C[64x64] += P[64,klen] * Q[64,klen]^T, row stride ld ----
// 128 ACTIVE threads (any extra threads in the block must have exited).
#define TILE_F (64 * 20)
template<bool PRECISE>
__device__ __forceinline__ void tile_gemm(const float* __restrict__ Pg0,
                                          const float* __restrict__ Qg0,
                                          int ld, int klen, float c[2][4][4],
                                          float* sP, float* sQ)
{
    const int tid = threadIdx.x;
    const int lane = tid & 31, wid = tid >> 5;
    const int wm = wid & 1, wn = wid >> 1;
    const int lrow = tid >> 2, lquad = tid & 3;

    uint32_t sPb = smem_to_u32(sP), sQb = smem_to_u32(sQ);
    const int NK = klen >> 4;
    const float* Pg = Pg0 + (size_t)lrow * ld + lquad * 4;
    const float* Qg = Qg0 + (size_t)lrow * ld + lquad * 4;
    const uint32_t spA0 = sPb + (uint32_t)(lrow * 20 + lquad * 4) * 4;
    const uint32_t spA1 = sPb + (uint32_t)((lrow + 32) * 20 + lquad * 4) * 4;
    const uint32_t sqA0 = sQb + (uint32_t)(lrow * 20 + lquad * 4) * 4;
    const uint32_t sqA1 = sQb + (uint32_t)((lrow + 32) * 20 + lquad * 4) * 4;

    {
        const float* p = Pg;  const float* q = Qg;
        cp16(spA0, p); cp16(spA1, p + (size_t)32 * ld);
        cp16(sqA0, q); cp16(sqA1, q + (size_t)32 * ld);
        CP_COMMIT();
        p = Pg + 16; q = Qg + 16;
        uint32_t off = TILE_F * 4;
        cp16(spA0 + off, p); cp16(spA1 + off, p + (size_t)32 * ld);
        cp16(sqA0 + off, q); cp16(sqA1 + off, q + (size_t)32 * ld);
        CP_COMMIT();
    }

    const int arow = lane >> 2, acol = lane & 3;
    for (int kt = 0; kt < NK; kt++) {
        CP_WAIT1();
        __syncthreads();
        const float* Pbuf = sP + (kt & 1) * TILE_F;
        const float* Qbuf = sQ + (kt & 1) * TILE_F;
        #pragma unroll
        for (int ks = 0; ks < 2; ks++) {
            const int k0 = ks * 8 + acol;
            uint32_t a[2][4], bq[4][2];
            uint32_t al[2][4], bl[4][2];
            #pragma unroll
            for (int mt = 0; mt < 2; mt++) {
                const int m = wm * 32 + mt * 16 + arow;
                float v0 = Pbuf[m * 20 + k0];
                float v1 = Pbuf[(m + 8) * 20 + k0];
                float v2 = Pbuf[m * 20 + k0 + 4];
                float v3 = Pbuf[(m + 8) * 20 + k0 + 4];
                a[mt][0] = f2tf(v0); a[mt][1] = f2tf(v1);
                a[mt][2] = f2tf(v2); a[mt][3] = f2tf(v3);
                if (PRECISE) {
                    al[mt][0] = f2tf(v0 - __uint_as_float(a[mt][0]));
                    al[mt][1] = f2tf(v1 - __uint_as_float(a[mt][1]));
                    al[mt][2] = f2tf(v2 - __uint_as_float(a[mt][2]));
                    al[mt][3] = f2tf(v3 - __uint_as_float(a[mt][3]));
                }
            }
            #pragma unroll
            for (int nt = 0; nt < 4; nt++) {
                const int n = wn * 32 + nt * 8 + arow;
                float w0 = Qbuf[n * 20 + k0];
                float w1 = Qbuf[n * 20 + k0 + 4];
                bq[nt][0] = f2tf(w0); bq[nt][1] = f2tf(w1);
                if (PRECISE) {
                    bl[nt][0] = f2tf(w0 - __uint_as_float(bq[nt][0]));
                    bl[nt][1] = f2tf(w1 - __uint_as_float(bq[nt][1]));
                }
            }
            #pragma unroll
            for (int mt = 0; mt < 2; mt++)
                #pragma unroll
                for (int nt = 0; nt < 4; nt++) {
                    if (PRECISE) {
                        mma_tf32(c[mt][nt], a[mt], bl[nt]);
                        mma_tf32(c[mt][nt], al[mt], bq[nt]);
                    }
                    mma_tf32(c[mt][nt], a[mt], bq[nt]);
                }
        }
        __syncthreads();
        if (kt + 2 < NK) {
            uint32_t off = (uint32_t)((kt & 1) * TILE_F) * 4;
            const float* p = Pg + (kt + 2) * 16;
            const float* q = Qg + (kt + 2) * 16;
            cp16(spA0 + off, p); cp16(spA1 + off, p + (size_t)32 * ld);
            cp16(sqA0 + off, q); cp16(sqA1 + off, q + (size_t)32 * ld);
        }
        CP_COMMIT();
    }
    CP_WAIT0();
}

// ================= prep: Ur/UrT + Vs + AT + acc =================
__global__ __launch_bounds__(256)
void prep_kernel(const float* __restrict__ rUr, const float* __restrict__ iUr,
                 const float* __restrict__ theta, const float* __restrict__ z,
                 const float* __restrict__ l1, const float* __restrict__ A,
                 const float* __restrict__ accnew_in, float* __restrict__ out_acc)
{
    __shared__ float t[32][33];
    const int bi = blockIdx.x;
    const int tid = threadIdx.x;

    if (bi < 64) {
        int e = bi * 256 + tid;
        int i = e >> 7, j = e & 127;
        float v, vt;
        if (i < 64) v = (j < 64) ? rUr[i * 64 + j] : -iUr[i * 64 + (j - 64)];
        else        v = (j < 64) ? iUr[(i - 64) * 64 + j] : rUr[(i - 64) * 64 + (j - 64)];
        g_Ur[e] = v;
        if (i < 64) vt = (j < 64) ? rUr[j * 64 + i] : iUr[(j - 64) * 64 + i];
        else        vt = (j < 64) ? -iUr[j * 64 + (i - 64)] : rUr[(j - 64) * 64 + (i - 64)];
        g_UrT[e] = vt;
    } else if (bi < 2112) {
        int e = (bi - 64) * 256 + tid;
        int m = e & (MM - 1);
        g_Vs[e] = theta[m] - z[e] - l1[e];
    } else if (bi < 4160) {
        int idx = bi - 2112;
        int n0 = (idx & 63) * 32, m0 = (idx >> 6) * 32;
        int tx = tid & 31, ty = tid >> 5;
        #pragma unroll
        for (int q = 0; q < 4; q++)
            t[ty + 8 * q][tx] = A[(size_t)(m0 + ty + 8 * q) * NN + n0 + tx];
        __syncthreads();
        #pragma unroll
        for (int q = 0; q < 4; q++)
            g_AT[(size_t)(n0 + ty + 8 * q) * MM + m0 + tx] = t[tx][ty + 8 * q];
    } else {
        if (tid == 0) out_acc[0] = accnew_in[0];
    }
}

// ================= fused K1a + gemm1: block-range dispatch =================
// blocks [0,1024): k1a (256 thr); blocks [1024,1536): split-K gemm1 (128 active thr)
#define FUSE_SMEM_FLOATS 7552
__global__ __launch_bounds__(256)
void k1a_g1_kernel(const float* __restrict__ XXp, const float* __restrict__ YYp,
                   const float* __restrict__ H,
                   const float* __restrict__ rUt, const float* __restrict__ iUt)
{
    __shared__ float smem[FUSE_SMEM_FLOATS];
    const int bi = blockIdx.x;
    const int tid = threadIdx.x;

    if (bi >= 1024) {
        // -------- gemm1 path: C1[kh][b][n] partials --------
        if (tid >= 128) return;
        const int idx = bi - 1024;
        const int kh = idx >> 8;
        const int rem = idx & 255;
        const int n0 = (rem & 31) * 64, b0 = (rem >> 5) * 64;
        float* sP = smem;
        float* sQ = smem + 2 * TILE_F;
        float c[2][4][4] = {};
        tile_gemm<false>(g_Vs + (size_t)b0 * MM + kh * 512,
                         g_AT + (size_t)n0 * MM + kh * 512, MM, 512, c, sP, sQ);

        float* Cp = g_C1 + (size_t)kh * BSZ * NN;
        const int lane = tid & 31, wid = tid >> 5;
        const int wm = wid & 1, wn = wid >> 1;
        #pragma unroll
        for (int mt = 0; mt < 2; mt++)
            #pragma unroll
            for (int rr = 0; rr < 2; rr++) {
                const int b = b0 + wm * 32 + mt * 16 + (lane >> 2) + rr * 8;
                float* Cb = Cp + (size_t)b * NN;
                #pragma unroll
                for (int nt = 0; nt < 4; nt++) {
                    const int n = n0 + wn * 32 + nt * 8 + (lane & 3) * 2;
                    *(float2*)(Cb + n) = make_float2(c[mt][nt][rr * 2 + 0],
                                                     c[mt][nt][rr * 2 + 1]);
                }
            }
        return;
    }

    // -------- k1a path --------
    float* sXXp  = smem;                 // 2304
    float* sUtXT = smem + 2304;          // 2304
    float* sS    = smem + 4608;          // 256
    float* sUt   = smem + 4864;          // 128
    float* sCh2  = smem + 4992;          // 2x 64*20 = 2560

    const int b = bi >> 1;
    const int half = bi & 1;

    const float* XXpb = XXp + (size_t)b * 16 * LT;
    for (int i = tid; i < 16 * LT; i += 256) sXXp[i] = XXpb[i];
    if (tid < 128) sUt[tid] = (tid < 64) ? rUt[tid] : iUt[tid - 64];

    const float* YYpb = YYp + (size_t)b * 128 * LT + (size_t)half * 64 * LT;
    const uint32_t chBase = smem_to_u32(sCh2);
    {
        int row = tid >> 2, seg = tid & 3;
        cp16(chBase + (uint32_t)(row * 20 + seg * 4) * 4, YYpb + row * LT + seg * 4);
    }
    CP_COMMIT();
    __syncthreads();

    for (int e = tid; e < 16 * LT; e += 256) {
        int i = e & 15, l = e >> 4;
        float acc = 0.f;
        if (i < 8) {
            #pragma unroll
            for (int k = 0; k < 8; k++) {
                acc += sUt[k * 8 + i] * sXXp[k * LT + l];
                acc += sUt[64 + k * 8 + i] * sXXp[(8 + k) * LT + l];
            }
        } else {
            int i2 = i - 8;
            #pragma unroll
            for (int k = 0; k < 8; k++) {
                acc -= sUt[64 + k * 8 + i2] * sXXp[k * LT + l];
                acc += sUt[k * 8 + i2] * sXXp[(8 + k) * LT + l];
            }
        }
        sUtXT[l * 16 + i] = acc;
    }
    __syncthreads();

    if (half == 0) {
        {
            int i = tid >> 4, j = tid & 15;
            float acc = 0.f;
            #pragma unroll 4
            for (int l = 0; l < LT; l++) acc += sUtXT[l * 16 + i] * sUtXT[l * 16 + j];
            sS[tid] = acc;
        }
        __syncthreads();

        if (tid < 128) {
            int q = tid & 63, k = q >> 3, t = q & 7;
            float v;
            if (tid < 64) v = sS[k * 16 + t] + sS[(8 + k) * 16 + 8 + t];
            else          v = sS[k * 16 + 8 + t] - sS[(8 + k) * 16 + t];
            g_EF[(size_t)b * 128 + tid] = v;
        }

        const float* Hb = H + (size_t)b * 1024;
        for (int e = tid; e < 1024; e += 256) {
            int c = e >> 7, k = e & 127;
            g_HGT[(size_t)b * 3072 + e] = Hb[k * 8 + c];
        }
    }

    // G^T[i][krow] for krow in [half*64, half*64+64) via 3xTF32 mma
    {
        const int lane = tid & 31, w = tid >> 5;
        const int arow = lane >> 2, acol = lane & 3;
        float cg[4] = {};
        for (int lc = 0; lc < 9; lc++) {
            if (lc + 1 < 9) {
                uint32_t off = (uint32_t)(((lc + 1) & 1) * (64 * 20)) * 4;
                int l0n = (lc + 1) * 16;
                int row = tid >> 2, seg = tid & 3;
                cp16(chBase + off + (uint32_t)(row * 20 + seg * 4) * 4,
                     YYpb + row * LT + l0n + seg * 4);
                CP_COMMIT();
                CP_WAIT1();
            } else {
                CP_WAIT0();
            }
            __syncthreads();
            const float* Ch = sCh2 + (lc & 1) * (64 * 20);
            #pragma unroll
            for (int ks = 0; ks < 2; ks++) {
                const int kg = lc * 16 + ks * 8 + acol;
                float av0 = sUtXT[kg * 16 + arow];
                float av1 = sUtXT[kg * 16 + arow + 8];
                float av2 = sUtXT[(kg + 4) * 16 + arow];
                float av3 = sUtXT[(kg + 4) * 16 + arow + 8];
                uint32_t ah[4] = {f2tf(av0), f2tf(av1), f2tf(av2), f2tf(av3)};
                uint32_t al[4] = {f2tf(av0 - __uint_as_float(ah[0])),
                                  f2tf(av1 - __uint_as_float(ah[1])),
                                  f2tf(av2 - __uint_as_float(ah[2])),
                                  f2tf(av3 - __uint_as_float(ah[3]))};
                const int n = w * 8 + arow;
                float bv0 = Ch[n * 20 + ks * 8 + acol];
                float bv1 = Ch[n * 20 + ks * 8 + acol + 4];
                uint32_t bh[2] = {f2tf(bv0), f2tf(bv1)};
                uint32_t bl[2] = {f2tf(bv0 - __uint_as_float(bh[0])),
                                  f2tf(bv1 - __uint_as_float(bh[1]))};
                mma_tf32(cg, ah, bl);
                mma_tf32(cg, al, bh);
                mma_tf32(cg, ah, bh);
            }
            __syncthreads();
        }
        float* dst = g_HGT + (size_t)b * 3072;
        const int col = half * 64 + w * 8 + (lane & 3) * 2;
        *(float2*)(dst + (8 + arow) * 128 + col) = make_float2(cg[0], cg[1]);
        *(float2*)(dst + (16 + arow) * 128 + col) = make_float2(cg[2], cg[3]);
    }
}

// ================= mega GEMM (3xTF32 precise) =================
__global__ __launch_bounds__(128)
void mega_gemm(const float* __restrict__ P, const float* __restrict__ Q,
               float* __restrict__ Out)
{
    __shared__ float buf[4 * TILE_F];
    const int m0 = blockIdx.x * 64;
    const int q0 = blockIdx.y * 64;
    float c[2][4][4] = {};
    tile_gemm<true>(P + (size_t)m0 * 128, Q + (size_t)q0 * 128, 128, 128, c,
                    buf, buf + 2 * TILE_F);
    __syncthreads();

    const int tid = threadIdx.x;
    const int lane = tid & 31, wid = tid >> 5;
    const int wm = wid & 1, wn = wid >> 1;
    #pragma unroll
    for (int mt = 0; mt < 2; mt++)
        #pragma unroll
        for (int nt = 0; nt < 4; nt++)
            #pragma unroll
            for (int k = 0; k < 4; k++) {
                int p = wm * 32 + mt * 16 + (lane >> 2) + (k >> 1) * 8;
                int q = wn * 32 + nt * 8 + (lane & 3) * 2 + (k & 1);
                buf[p * 68 + q] = c[mt][nt][k];
            }
    __syncthreads();
    #pragma unroll 4
    for (int i = 0; i < 32; i++) {
        int idx = i * 128 + tid;
        int p = idx & 63, q = idx >> 6;
        Out[(size_t)(q0 + q) * 128 + m0 + p] = buf[p * 68 + q];
    }
}

// ================= K3: Hv, D, Hvest, soft-threshold (512 thr) =================
__global__ __launch_bounds__(512)
void k3_kernel(const float* __restrict__ sigma2,
               const float* __restrict__ rUt, const float* __restrict__ iUt,
               const float* __restrict__ tao_p, const float* __restrict__ eps_p)
{
    __shared__ float sTc[24 * 128];
    __shared__ float sEF[128];
    __shared__ float sUt[128];
    __shared__ float sHv[1024];
    __shared__ float sHve[1024];

    const int b = blockIdx.x;
    const int tid = threadIdx.x;
    const float tao = tao_p[0];

    for (int i = tid; i < 3072; i += 512) sTc[i] = g_T[(size_t)b * 3072 + i];
    if (tid < 128) {
        sEF[tid] = g_EF[(size_t)b * 128 + tid];
        sUt[tid] = (tid < 64) ? rUt[tid] : iUt[tid - 64];
    }
    __syncthreads();

    {
        const int r = tid >> 2, c0 = (tid & 3) * 2;
        #pragma unroll
        for (int c = c0; c < c0 + 2; c++) {
            float acc = 0.f;
            if (r < 64) {
                #pragma unroll
                for (int k = 0; k < 8; k++)
                    acc += sTc[k * 128 + r] * sUt[k * 8 + c] - sTc[k * 128 + 64 + r] * sUt[64 + k * 8 + c];
            } else {
                #pragma unroll
                for (int k = 0; k < 8; k++)
                    acc += sTc[k * 128 + r] * sUt[k * 8 + c] + sTc[k * 128 + r - 64] * sUt[64 + k * 8 + c];
            }
            sHv[r * 8 + c] = acc;
        }
    }
    __syncthreads();

    {
        const int r = tid >> 2, t0 = (tid & 3) * 2;
        #pragma unroll
        for (int t = t0; t < t0 + 2; t++) {
            float s = 0.f;
            if (r < 64) {
                #pragma unroll
                for (int k = 0; k < 8; k++)
                    s += sHv[r * 8 + k] * sEF[k * 8 + t] + sHv[(64 + r) * 8 + k] * sEF[64 + k * 8 + t];
                s -= sTc[(8 + t) * 128 + r] + sTc[(16 + t) * 128 + 64 + r];
            } else {
                int r2 = r - 64;
                #pragma unroll
                for (int k = 0; k < 8; k++)
                    s += sHv[r * 8 + k] * sEF[k * 8 + t] - sHv[r2 * 8 + k] * sEF[64 + k * 8 + t];
                s -= sTc[(8 + t) * 128 + r] - sTc[(16 + t) * 128 + r2];
            }
            sHve[r * 8 + t] = sHv[r * 8 + t] - tao * s;
        }
    }
    __syncthreads();

    {
        float thr = tao * eps_p[0] * sigma2[b];
        if (tid < 512) {
            int e = tid;
            float re = sHve[e], im = sHve[e + 512];
            float mag = sqrtf(re * re + im * im);
            float s = fmaxf(mag - thr, 0.f) / mag;
            sHve[e] = re * s;
            sHve[e + 512] = im * s;
        }
    }
    __syncthreads();

    for (int i = tid; i < 1024; i += 512) {
        int c = i >> 7, r = i & 127;
        g_HveT[(size_t)b * 1024 + i] = sHve[r * 8 + c];
    }
}

// ================= K5: H_new, W, WTW, F via mma (512 thr) =================
#define CPAD 136
#define CHK (16 * CPAD)
__global__ __launch_bounds__(512)
void k5_kernel(const float* __restrict__ X, const float* __restrict__ Y,
               const float* __restrict__ lambda_W,
               const float* __restrict__ rUt, const float* __restrict__ iUt,
               const float* __restrict__ factor_p,
               float* __restrict__ out_Hnew, float* __restrict__ out_lamW)
{
    __shared__ float sUc[1024];
    __shared__ float sUt[128];
    __shared__ float sHN[1024];
    __shared__ float sW[128 * 24];
    __shared__ float sWTW[256];
    __shared__ float sX[2048];
    __shared__ float sCh[2][CHK];

    const int b = blockIdx.x;
    const int tid = threadIdx.x;

    const float* Yb = Y + (size_t)b * 128 * LD;
    const uint32_t chBase = smem_to_u32(sCh);
    {
        int row = tid >> 5, seg = tid & 31;
        cp16(chBase + (uint32_t)(row * CPAD + seg * 4) * 4, Yb + row * 128 + seg * 4);
    }
    CP_COMMIT();

    for (int i = tid; i < 1024; i += 512) sUc[i] = g_UrHvT[(size_t)b * 1024 + i];
    {
        const float* Xb = X + (size_t)b * 16 * LD;
        for (int e = tid; e < 2048; e += 512) sX[e] = Xb[e];
    }
    if (tid < 128) sUt[tid] = (tid < 64) ? rUt[tid] : iUt[tid - 64];
    __syncthreads();

    {
        const int r = tid >> 2, c0 = (tid & 3) * 2;
        #pragma unroll
        for (int c = c0; c < c0 + 2; c++) {
            float acc = 0.f;
            if (r < 64) {
                #pragma unroll
                for (int k = 0; k < 8; k++)
                    acc += sUc[k * 128 + r] * sUt[c * 8 + k] + sUc[k * 128 + 64 + r] * sUt[64 + c * 8 + k];
            } else {
                #pragma unroll
                for (int k = 0; k < 8; k++)
                    acc += sUc[k * 128 + r] * sUt[c * 8 + k] - sUc[k * 128 + r - 64] * sUt[64 + c * 8 + k];
            }
            sHN[r * 8 + c] = acc;
            out_Hnew[(size_t)b * 1024 + r * 8 + c] = acc;
        }
    }
    __syncthreads();

    for (int e = tid; e < 2048; e += 512) {
        int r = e >> 4, i = e & 15;
        float v;
        if (r < 64) v = (i < 8) ? sHN[r * 8 + i] : -sHN[(64 + r) * 8 + (i - 8)];
        else        v = (i < 8) ? sHN[r * 8 + i] : sHN[(r - 64) * 8 + (i - 8)];
        sW[r * 24 + i] = v;
    }
    __syncthreads();

    if (tid < 256) {
        int i = tid >> 4, j = tid & 15;
        float acc = 0.f;
        #pragma unroll 4
        for (int r = 0; r < 128; r++) acc += sW[r * 24 + i] * sW[r * 24 + j];
        sWTW[tid] = acc;
    }
    __syncthreads();

    {
        const int lane = tid & 31, w = tid >> 5;
        const int arow = lane >> 2, acol = lane & 3;
        float cf[4] = {};
        for (int rc = 0; rc < 8; rc++) {
            if (rc + 1 < 8) {
                uint32_t off = (uint32_t)(((rc + 1) & 1) * CHK) * 4;
                const float* src = Yb + (rc + 1) * 16 * 128;
                int row = tid >> 5, seg = tid & 31;
                cp16(chBase + off + (uint32_t)(row * CPAD + seg * 4) * 4,
                     src + row * 128 + seg * 4);
                CP_COMMIT();
                CP_WAIT1();
            } else {
                CP_WAIT0();
            }
            __syncthreads();
            const float* Ch = sCh[rc & 1];
            #pragma unroll
            for (int ks = 0; ks < 2; ks++) {
                const int kg = rc * 16 + ks * 8 + acol;
                float av0 = sW[kg * 24 + arow];
                float av1 = sW[kg * 24 + arow + 8];
                float av2 = sW[(kg + 4) * 24 + arow];
                float av3 = sW[(kg + 4) * 24 + arow + 8];
                uint32_t ah[4] = {f2tf(av0), f2tf(av1), f2tf(av2), f2tf(av3)};
                uint32_t al[4] = {f2tf(av0 - __uint_as_float(ah[0])),
                                  f2tf(av1 - __uint_as_float(ah[1])),
                                  f2tf(av2 - __uint_as_float(ah[2])),
                                  f2tf(av3 - __uint_as_float(ah[3]))};
                const int n = w * 8 + arow;
                float bv0 = Ch[(ks * 8 + acol) * CPAD + n];
                float bv1 = Ch[(ks * 8 + acol + 4) * CPAD + n];
                uint32_t bh[2] = {f2tf(bv0), f2tf(bv1)};
                uint32_t bl[2] = {f2tf(bv0 - __uint_as_float(bh[0])),
                                  f2tf(bv1 - __uint_as_float(bh[1]))};
                mma_tf32(cf, ah, bl);
                mma_tf32(cf, al, bh);
                mma_tf32(cf, ah, bh);
            }
            __syncthreads();
        }

        float lamW = factor_p[0] * lambda_W[b];
        float* Fb = g_F + (size_t)b * NN;
        float wt0[16], wt1[16];
        #pragma unroll
        for (int j = 0; j < 16; j++) {
            wt0[j] = sWTW[arow * 16 + j];
            wt1[j] = sWTW[(arow + 8) * 16 + j];
        }
        #pragma unroll
        for (int ls = 0; ls < 2; ls++) {
            const int l = w * 8 + (lane & 3) * 2 + ls;
            float xi[16];
            #pragma unroll
            for (int j = 0; j < 16; j++) xi[j] = sX[j * 128 + l];
            float v0 = cf[ls] + lamW * xi[arow];
            float v1 = cf[2 + ls] + lamW * xi[arow + 8];
            #pragma unroll
            for (int j = 0; j < 16; j++) {
                v0 -= wt0[j] * xi[j];
                v1 -= wt1[j] * xi[j];
            }
            *(float2*)(Fb + l * 16 + arow * 2) =
                make_float2(2.f * lamW - 2.f * SQ2F * v0,
                            2.f * lamW - 2.f * SQ2F * v1);
        }
        if (tid == 0) out_lamW[b] = lamW;
    }
}

// ================= epi1x: partials -> u_new + X_new + XXp (per-batch, fused transpose) =================
__global__ __launch_bounds__(512)
void epi1x_kernel(const float* __restrict__ La, const float* __restrict__ lamWv,
                  const float* __restrict__ rho_p, const float* __restrict__ kappa_p,
                  const float* __restrict__ rXp, const float* __restrict__ iXp,
                  float* __restrict__ out_u, float* __restrict__ out_X,
                  float* __restrict__ out_XXp)
{
    __shared__ float st[16 * 132];
    const int b = blockIdx.x;
    const int tid = threadIdx.x;
    const int n0 = tid * 4;
    const size_t base = (size_t)b * NN + n0;

    float4 p0 = *(const float4*)(g_C1 + base);
    float4 p1 = *(const float4*)(g_C1 + (size_t)BSZ * NN + base);
    float4 fb = *(const float4*)(g_F + base);
    float4 la = *(const float4*)(La + n0);
    const float rho = rho_p[0], kappa = kappa_p[0];
    const float lamW = lamWv[b];
    const float den = 4.f * lamW - 2.f * kappa;
    float4 u;
    u.x = fminf(fmaxf((rho * (p0.x + p1.x) + fb.x - kappa) / (rho * la.x + den), 0.f), 1.f);
    u.y = fminf(fmaxf((rho * (p0.y + p1.y) + fb.y - kappa) / (rho * la.y + den), 0.f), 1.f);
    u.z = fminf(fmaxf((rho * (p0.z + p1.z) + fb.z - kappa) / (rho * la.z + den), 0.f), 1.f);
    u.w = fminf(fmaxf((rho * (p0.w + p1.w) + fb.w - kappa) / (rho * la.w + den), 0.f), 1.f);
    *(float4*)(out_u + base) = u;

    {
        const int l = n0 >> 4;
        const int t0 = (n0 >> 1) & 7;
        st[t0 * 132 + l]       = (1.f - 2.f * u.x) * INV_SQ2F;
        st[(8 + t0) * 132 + l] = (1.f - 2.f * u.y) * INV_SQ2F;
        st[(t0 + 1) * 132 + l] = (1.f - 2.f * u.z) * INV_SQ2F;
        st[(9 + t0) * 132 + l] = (1.f - 2.f * u.w) * INV_SQ2F;
    }
    __syncthreads();

    float* Xb = out_X + (size_t)b * 2048;
    float* XXb = out_XXp + (size_t)b * 2304;
    for (int e = tid; e < 2048; e += 512) {
        int row = e >> 7, l = e & 127;
        float v = st[row * 132 + l];
        Xb[e] = v;
        XXb[row * 144 + l] = v;
    }
    if (tid < 256) {
        int e = tid;
        int tt = e >> 5, ci = (e >> 4) & 1, lp = e & 15;
        float v = ci ? iXp[(size_t)b * 128 + tt * 16 + lp]
                     : rXp[(size_t)b * 128 + tt * 16 + lp];
        XXb[(ci * 8 + tt) * 144 + 128 + lp] = v;
    }
}

// ================= split-K(4) MMA GEMM2: partial C[b,m] =================
__global__ __launch_bounds__(128)
void mma_gemm2(const float* __restrict__ A, const float* __restrict__ u_in)
{
    __shared__ float sP[2 * TILE_F];
    __shared__ float sQ[2 * TILE_F];
    const int m0 = blockIdx.x * 64, b0 = blockIdx.y * 64, kh = blockIdx.z;
    float c[2][4][4] = {};
    tile_gemm<false>(u_in + (size_t)b0 * NN + kh * 512,
                     A + (size_t)m0 * NN + kh * 512, NN, 512, c, sP, sQ);

    float* Cp = g_C2 + (size_t)kh * BSZ * MM;
    const int lane = threadIdx.x & 31, wid = threadIdx.x >> 5;
    const int wm = wid & 1, wn = wid >> 1;
    #pragma unroll
    for (int mt = 0; mt < 2; mt++)
        #pragma unroll
        for (int rr = 0; rr < 2; rr++) {
            const int b = b0 + wm * 32 + mt * 16 + (lane >> 2) + rr * 8;
            float* Cb = Cp + (size_t)b * MM;
            #pragma unroll
            for (int nt = 0; nt < 4; nt++) {
                const int m = m0 + wn * 32 + nt * 8 + (lane & 3) * 2;
                *(float2*)(Cb + m) = make_float2(c[mt][nt][rr * 2 + 0],
                                                 c[mt][nt][rr * 2 + 1]);
            }
        }
}

// ================= epi2: combine 4 partials -> z_new, lambda1_new =================
__global__ void epi2_kernel(const float* __restrict__ theta, const float* __restrict__ z_old,
                            const float* __restrict__ l1_old, const float* __restrict__ relax_p,
                            const float* __restrict__ acc_p,
                            float* __restrict__ out_z, float* __restrict__ out_l1)
{
    int idx = blockIdx.x * blockDim.x + threadIdx.x;
    if (idx >= BSZ * MM / 4) return;
    float4 p0 = ((const float4*)g_C2)[idx];
    float4 p1 = ((const float4*)(g_C2 + (size_t)BSZ * MM))[idx];
    float4 p2 = ((const float4*)(g_C2 + (size_t)2 * BSZ * MM))[idx];
    float4 p3 = ((const float4*)(g_C2 + (size_t)3 * BSZ * MM))[idx];
    int e4 = idx * 4;
    int m = e4 & 1023;
    float relax = relax_p[0], acc = acc_p[0];
    float4 th = *(const float4*)(theta + m);
    float4 zo = ((const float4*)z_old)[idx];
    float4 lo = ((const float4*)l1_old)[idx];
    float4 zn, ln;
    #define DO(comp) { \
        float ct = (p0.comp + p1.comp) + (p2.comp + p3.comp); \
        float zt = th.comp - relax * ct - (1.f - relax) * (th.comp - zo.comp) - lo.comp; \
        float z1 = fmaxf(zt, 0.f); \
        float l1v = z1 - zt; \
        zn.comp = z1 + acc * (z1 - zo.comp); \
        ln.comp = l1v + acc * (l1v - lo.comp); }
    DO(x) DO(y) DO(z) DO(w)
    #undef DO
    ((float4*)out_z)[idx] = zn;
    ((float4*)out_l1)[idx] = ln;
}

// ================= launch =================
extern "C" void kernel_launch(void* const* d_in, const int* in_sizes, int n_in,
                              void* d_out, int out_size) {
    (void)in_sizes; (void)n_in; (void)out_size;
    const float* sigma2   = (const float*)d_in[0];
    const float* X        = (const float*)d_in[1];
    const float* XXp      = (const float*)d_in[2];
    const float* Y        = (const float*)d_in[3];
    const float* YYp      = (const float*)d_in[4];
    const float* rXp      = (const float*)d_in[5];
    const float* iXp      = (const float*)d_in[6];
    const float* H        = (const float*)d_in[7];
    const float* lambda_W = (const float*)d_in[8];
    const float* z        = (const float*)d_in[10];
    const float* lambda1  = (const float*)d_in[11];
    const float* acc_new  = (const float*)d_in[12];
    const float* A        = (const float*)d_in[13];
    const float* Lambda_A = (const float*)d_in[14];
    const float* theta    = (const float*)d_in[15];
    const float* rUr      = (const float*)d_in[16];
    const float* iUr      = (const float*)d_in[17];
    const float* rUt      = (const float*)d_in[18];
    const float* iUt      = (const float*)d_in[19];
    const float* rho      = (const float*)d_in[20];
    const float* kappa    = (const float*)d_in[21];
    const float* epsilon  = (const float*)d_in[22];
    const float* tao      = (const float*)d_in[23];
    const float* factor   = (const float*)d_in[24];
    const float* relax    = (const float*)d_in[25];
    const float* acc      = (const float*)d_in[26];

    float* out = (float*)d_out;
    float* out_X    = out;
    float* out_XXp  = out + 1048576;
    float* out_H    = out + 2228224;
    float* out_lamW = out + 2752512;
    float* out_u    = out + 2753024;
    float* out_z    = out + 3801600;
    float* out_l1   = out + 4325888;
    float* out_acc  = out + 4850176;

    float* dg_Ur, *dg_UrT, *dg_HGT, *dg_T, *dg_HveT, *dg_UrHvT;
    cudaGetSymbolAddress((void**)&dg_Ur, g_Ur);
    cudaGetSymbolAddress((void**)&dg_UrT, g_UrT);
    cudaGetSymbolAddress((void**)&dg_HGT, g_HGT);
    cudaGetSymbolAddress((void**)&dg_T, g_T);
    cudaGetSymbolAddress((void**)&dg_HveT, g_HveT);
    cudaGetSymbolAddress((void**)&dg_UrHvT, g_UrHvT);

    prep_kernel<<<4161, 256>>>(rUr, iUr, theta, z, lambda1, A, acc_new, out_acc);
    k1a_g1_kernel<<<1536, 256>>>(XXp, YYp, H, rUt, iUt);
    mega_gemm<<<dim3(2, BSZ * 24 / 64), 128>>>(dg_UrT, dg_HGT, dg_T);
    k3_kernel<<<BSZ, 512>>>(sigma2, rUt, iUt, tao, epsilon);
    mega_gemm<<<dim3(2, BSZ * 8 / 64), 128>>>(dg_Ur, dg_HveT, dg_UrHvT);
    k5_kernel<<<BSZ, 512>>>(X, Y, lambda_W, rUt, iUt, factor, out_H, out_lamW);
    epi1x_kernel<<<BSZ, 512>>>(Lambda_A, out_lamW, rho, kappa, rXp, iXp,
                               out_u, out_X, out_XXp);
    mma_gemm2<<<dim3(MM / 64, BSZ / 64, 4), 128>>>(A, out_u);
    epi2_kernel<<<(BSZ * MM / 4 + 255) / 256, 256>>>(theta, z, lambda1, relax, acc,
                                                     out_z, out_l1);
}